// round 1
// baseline (speedup 1.0000x reference)
#include <cuda_runtime.h>
#include <cuda_bf16.h>
#include <math.h>

// ---------------------------------------------------------------------------
// GraphSimilarity: 2x { encoder MLP (2 GEMMs) -> GCN -> GCN -> mean pool }
//                  -> similarity MLP -> scalar
// N=50000, D=H=128, E=800000 (sizes taken from in_sizes at runtime, buffers
// statically sized for the known problem).
// ---------------------------------------------------------------------------

#define MAXN 50000
#define MAXE 800000
#define HDIM 128

__device__ float g_bufA[MAXN * HDIM];
__device__ float g_bufB[MAXN * HDIM];
__device__ int   g_deg[MAXN];
__device__ float g_dis[MAXN];
__device__ int   g_offs[MAXN + 1];
__device__ int   g_cursor[MAXN];
__device__ int   g_csr_col[MAXE];
__device__ float g_gsum[2 * HDIM];

// ---------------------------------------------------------------------------
// GEMM: C[M,128] = act( A'[M,128] @ W[128,128] + bias )
//   A'[m,k] = IN_TRANSFORM ? relu(dis[m] * A[m,k]) : A[m,k]
//   act = RELU_OUT ? relu : identity
// Tiling: BM=128, BN=128 (full), BK=8; 256 threads; 8x8 micro-tile per thread.
// ---------------------------------------------------------------------------
template<int RELU_OUT, int IN_TRANSFORM>
__global__ __launch_bounds__(256)
void k_gemm(const float* __restrict__ A, const float* __restrict__ W,
            const float* __restrict__ bias, float* __restrict__ C,
            const float* __restrict__ dis, int M)
{
    const int bm = blockIdx.x * 128;

    __shared__ float As[8][132];   // padded to kill STS bank conflicts
    __shared__ float Bs[8][128];

    const int tid = threadIdx.x;           // 0..255
    const int tx  = tid & 15;              // 0..15 -> output cols tx*8..+7
    const int ty  = tid >> 4;              // 0..15 -> output rows ty*8..+7

    // A-tile load mapping: row = tid/2 (0..127), k-segment = (tid&1)*4
    const int arow = tid >> 1;
    const int aseg = (tid & 1) * 4;
    const int grow = bm + arow;
    float dval = 1.0f;
    if (IN_TRANSFORM && grow < M) dval = dis[grow];

    // W-tile load mapping: k = tid/32 (0..7), col = (tid&31)*4
    const int bk = tid >> 5;
    const int bc = (tid & 31) * 4;

    float acc[8][8];
#pragma unroll
    for (int i = 0; i < 8; i++)
#pragma unroll
        for (int j = 0; j < 8; j++) acc[i][j] = 0.0f;

    for (int k0 = 0; k0 < 128; k0 += 8) {
        float4 av = make_float4(0.f, 0.f, 0.f, 0.f);
        if (grow < M)
            av = *reinterpret_cast<const float4*>(A + (size_t)grow * 128 + k0 + aseg);
        if (IN_TRANSFORM) {
            av.x = fmaxf(av.x * dval, 0.f);
            av.y = fmaxf(av.y * dval, 0.f);
            av.z = fmaxf(av.z * dval, 0.f);
            av.w = fmaxf(av.w * dval, 0.f);
        }
        As[aseg + 0][arow] = av.x;
        As[aseg + 1][arow] = av.y;
        As[aseg + 2][arow] = av.z;
        As[aseg + 3][arow] = av.w;

        *reinterpret_cast<float4*>(&Bs[bk][bc]) =
            *reinterpret_cast<const float4*>(W + (size_t)(k0 + bk) * 128 + bc);

        __syncthreads();

#pragma unroll
        for (int k = 0; k < 8; k++) {
            float a[8], b[8];
            *reinterpret_cast<float4*>(a)     = *reinterpret_cast<float4*>(&As[k][ty * 8]);
            *reinterpret_cast<float4*>(a + 4) = *reinterpret_cast<float4*>(&As[k][ty * 8 + 4]);
            *reinterpret_cast<float4*>(b)     = *reinterpret_cast<float4*>(&Bs[k][tx * 8]);
            *reinterpret_cast<float4*>(b + 4) = *reinterpret_cast<float4*>(&Bs[k][tx * 8 + 4]);
#pragma unroll
            for (int i = 0; i < 8; i++)
#pragma unroll
                for (int j = 0; j < 8; j++)
                    acc[i][j] = fmaf(a[i], b[j], acc[i][j]);
        }
        __syncthreads();
    }

    // epilogue
#pragma unroll
    for (int i = 0; i < 8; i++) {
        int row = bm + ty * 8 + i;
        if (row >= M) break;
#pragma unroll
        for (int j = 0; j < 8; j += 4) {
            int col = tx * 8 + j;
            float4 v;
            v.x = acc[i][j + 0] + __ldg(bias + col + 0);
            v.y = acc[i][j + 1] + __ldg(bias + col + 1);
            v.z = acc[i][j + 2] + __ldg(bias + col + 2);
            v.w = acc[i][j + 3] + __ldg(bias + col + 3);
            if (RELU_OUT) {
                v.x = fmaxf(v.x, 0.f); v.y = fmaxf(v.y, 0.f);
                v.z = fmaxf(v.z, 0.f); v.w = fmaxf(v.w, 0.f);
            }
            *reinterpret_cast<float4*>(C + (size_t)row * 128 + col) = v;
        }
    }
}

// ---------------------------------------------------------------------------
// degree count over rows
// ---------------------------------------------------------------------------
__global__ void k_deg(const int* __restrict__ ei, int E, int* __restrict__ deg)
{
    int e = blockIdx.x * blockDim.x + threadIdx.x;
    if (e < E) atomicAdd(&deg[ei[e]], 1);
}

__global__ void k_dis(const int* __restrict__ deg, float* __restrict__ dis, int n)
{
    int i = blockIdx.x * blockDim.x + threadIdx.x;
    if (i < n) {
        int d = deg[i];
        dis[i] = (d > 0) ? rsqrtf((float)d) : 0.0f;
    }
}

// single-block exclusive scan -> offs[0..n], offs[0]=0
__global__ void k_scan(const int* __restrict__ deg, int* __restrict__ offs, int n)
{
    __shared__ int sm[1024];
    __shared__ int carry;
    if (threadIdx.x == 0) carry = 0;
    __syncthreads();
    for (int base = 0; base < n; base += 1024) {
        int i = base + threadIdx.x;
        int v = (i < n) ? deg[i] : 0;
        sm[threadIdx.x] = v;
        __syncthreads();
        for (int off = 1; off < 1024; off <<= 1) {
            int t = (threadIdx.x >= off) ? sm[threadIdx.x - off] : 0;
            __syncthreads();
            sm[threadIdx.x] += t;
            __syncthreads();
        }
        if (i < n) offs[i + 1] = carry + sm[threadIdx.x];   // inclusive -> offs[i+1]
        __syncthreads();
        if (threadIdx.x == 1023) carry += sm[1023];
        __syncthreads();
    }
    if (threadIdx.x == 0) offs[0] = 0;
}

__global__ void k_scatter(const int* __restrict__ ei, int E,
                          const int* __restrict__ offs, int* __restrict__ cursor,
                          int* __restrict__ cols)
{
    int e = blockIdx.x * blockDim.x + threadIdx.x;
    if (e >= E) return;
    int r = ei[e];
    int c = ei[E + e];
    int pos = offs[r] + atomicAdd(&cursor[r], 1);
    cols[pos] = c;
}

// ---------------------------------------------------------------------------
// CSR aggregation: agg[n,:] = sum_{c in nbrs(n)} dis[c] * h[c,:]
// one warp per node; 4 floats (1 float4) per lane = 128 cols.
// ---------------------------------------------------------------------------
__global__ void k_aggregate(const float* __restrict__ h,
                            const int* __restrict__ offs,
                            const int* __restrict__ cols,
                            const float* __restrict__ dis,
                            float* __restrict__ agg, int n)
{
    int warp = (blockIdx.x * blockDim.x + threadIdx.x) >> 5;
    int lane = threadIdx.x & 31;
    if (warp >= n) return;
    int s = offs[warp], e = offs[warp + 1];
    float4 acc = make_float4(0.f, 0.f, 0.f, 0.f);
    for (int i = s; i < e; i++) {
        int c = __ldg(cols + i);
        float nr = __ldg(dis + c);
        float4 v = *reinterpret_cast<const float4*>(h + (size_t)c * 128 + lane * 4);
        acc.x = fmaf(nr, v.x, acc.x);
        acc.y = fmaf(nr, v.y, acc.y);
        acc.z = fmaf(nr, v.z, acc.z);
        acc.w = fmaf(nr, v.w, acc.w);
    }
    *reinterpret_cast<float4*>(agg + (size_t)warp * 128 + lane * 4) = acc;
}

// ---------------------------------------------------------------------------
// pooling: gsum[col] += sum_n relu(dis[n] * agg[n,col])
// ---------------------------------------------------------------------------
__global__ void k_pool(const float* __restrict__ agg, const float* __restrict__ dis,
                       float* __restrict__ gsum, int n)
{
    int col = threadIdx.x & 127;
    int sub = threadIdx.x >> 7;   // 0..1
    float acc = 0.0f;
    for (int row = blockIdx.x * 2 + sub; row < n; row += gridDim.x * 2) {
        float d = dis[row];
        float v = d * agg[(size_t)row * 128 + col];
        acc += fmaxf(v, 0.f);
    }
    __shared__ float sm[256];
    sm[threadIdx.x] = acc;
    __syncthreads();
    if (threadIdx.x < 128)
        atomicAdd(&gsum[col], sm[threadIdx.x] + sm[threadIdx.x + 128]);
}

// ---------------------------------------------------------------------------
// final MLP: c = [g1, g2, |g1-g2|, g1*g2] (4H=512) -> relu(c@W1+b1) @ W2 + b2
// ---------------------------------------------------------------------------
__global__ void k_final(const float* __restrict__ gsum,
                        const float* __restrict__ w1, const float* __restrict__ b1,
                        const float* __restrict__ w2, const float* __restrict__ b2,
                        float* __restrict__ out, float invN)
{
    __shared__ float cv[512];
    __shared__ float red[128];
    int t = threadIdx.x;  // 128 threads
    float a = gsum[t] * invN;
    float b = gsum[128 + t] * invN;
    cv[t]       = a;
    cv[128 + t] = b;
    cv[256 + t] = fabsf(a - b);
    cv[384 + t] = a * b;
    __syncthreads();
    float acc = b1[t];
    for (int k = 0; k < 512; k++)
        acc = fmaf(cv[k], w1[k * 128 + t], acc);
    acc = fmaxf(acc, 0.f);
    red[t] = acc * w2[t];
    __syncthreads();
    for (int s = 64; s > 0; s >>= 1) {
        if (t < s) red[t] += red[t + s];
        __syncthreads();
    }
    if (t == 0) out[0] = red[0] + b2[0];
}

// ---------------------------------------------------------------------------
// launch
// ---------------------------------------------------------------------------
extern "C" void kernel_launch(void* const* d_in, const int* in_sizes, int n_in,
                              void* d_out, int out_size)
{
    const float* x1  = (const float*)d_in[0];
    const int*   ei1 = (const int*)d_in[1];
    const float* x2  = (const float*)d_in[2];
    const int*   ei2 = (const int*)d_in[3];
    const float* enc_w1 = (const float*)d_in[4];
    const float* enc_b1 = (const float*)d_in[5];
    const float* enc_w2 = (const float*)d_in[6];
    const float* enc_b2 = (const float*)d_in[7];
    const float* conv1_w = (const float*)d_in[8];
    const float* conv1_b = (const float*)d_in[9];
    const float* conv2_w = (const float*)d_in[10];
    const float* conv2_b = (const float*)d_in[11];
    const float* sim_w1 = (const float*)d_in[12];
    const float* sim_b1 = (const float*)d_in[13];
    const float* sim_w2 = (const float*)d_in[14];
    const float* sim_b2 = (const float*)d_in[15];

    const int n = in_sizes[0] / HDIM;   // 50000
    const int E = in_sizes[1] / 2;      // 800000

    float *bufA, *bufB, *dis, *gsum;
    int *deg, *offs, *cursor, *csr_col;
    cudaGetSymbolAddress((void**)&bufA,    g_bufA);
    cudaGetSymbolAddress((void**)&bufB,    g_bufB);
    cudaGetSymbolAddress((void**)&deg,     g_deg);
    cudaGetSymbolAddress((void**)&dis,     g_dis);
    cudaGetSymbolAddress((void**)&offs,    g_offs);
    cudaGetSymbolAddress((void**)&cursor,  g_cursor);
    cudaGetSymbolAddress((void**)&csr_col, g_csr_col);
    cudaGetSymbolAddress((void**)&gsum,    g_gsum);

    const int gemmBlocks = (n + 127) / 128;
    const int eBlocks    = (E + 255) / 256;
    const int nBlocks    = (n + 255) / 256;
    const int aggBlocks  = (n * 32 + 255) / 256;

    cudaMemsetAsync(gsum, 0, 2 * HDIM * sizeof(float));

    for (int g = 0; g < 2; g++) {
        const float* x  = (g == 0) ? x1 : x2;
        const int*   ei = (g == 0) ? ei1 : ei2;

        // --- CSR build (shared by both GCN layers) ---
        cudaMemsetAsync(deg, 0, n * sizeof(int));
        cudaMemsetAsync(cursor, 0, n * sizeof(int));
        k_deg<<<eBlocks, 256>>>(ei, E, deg);
        k_dis<<<nBlocks, 256>>>(deg, dis, n);
        k_scan<<<1, 1024>>>(deg, offs, n);
        k_scatter<<<eBlocks, 256>>>(ei, E, offs, cursor, csr_col);

        // --- encoder MLP ---
        k_gemm<1, 0><<<gemmBlocks, 256>>>(x,    enc_w1, enc_b1, bufA, dis, n);
        k_gemm<0, 0><<<gemmBlocks, 256>>>(bufA, enc_w2, enc_b2, bufB, dis, n);

        // --- GCN layer 1: h = bufB @ conv1_w + b, agg = sum dis[c]*h[c] ---
        k_gemm<0, 0><<<gemmBlocks, 256>>>(bufB, conv1_w, conv1_b, bufA, dis, n);
        k_aggregate<<<aggBlocks, 256>>>(bufA, offs, csr_col, dis, bufB, n);

        // --- GCN layer 2: input transform relu(dis[m]*agg) fused into GEMM ---
        k_gemm<0, 1><<<gemmBlocks, 256>>>(bufB, conv2_w, conv2_b, bufA, dis, n);
        k_aggregate<<<aggBlocks, 256>>>(bufA, offs, csr_col, dis, bufB, n);

        // --- mean pool (relu + dis scaling fused) ---
        k_pool<<<256, 256>>>(bufB, dis, gsum + g * HDIM, n);
    }

    k_final<<<1, 128>>>(gsum, sim_w1, sim_b1, sim_w2, sim_b2,
                        (float*)d_out, 1.0f / (float)n);
}

// round 4
// speedup vs baseline: 1.2573x; 1.2573x over previous
#include <cuda_runtime.h>
#include <cuda_bf16.h>
#include <math.h>
#include <stdint.h>

// ---------------------------------------------------------------------------
// GraphSimilarity: 2x { encoder MLP (2 GEMMs) -> GCN -> GCN -> mean pool }
//                  -> similarity MLP -> scalar
// GEMMs on classic tensor-core mma.sync (bf16 3-term split, fp32 accumulate).
// (tcgen05 is unavailable: harness PTX target is compute_103, not 103a.)
// ---------------------------------------------------------------------------

#define MAXN 50000
#define MAXE 800000
#define HDIM 128

__device__ __align__(16) float g_bufA[MAXN * HDIM];
__device__ __align__(16) float g_bufB[MAXN * HDIM];
__device__ int   g_deg[MAXN];
__device__ float g_dis[MAXN];
__device__ int   g_offs[MAXN + 1];
__device__ int   g_cursor[MAXN];
__device__ int   g_csr_col[MAXE];
__device__ float g_gsum[2 * HDIM];
// bf16 weight splits: 8 images (4 weights x hi/lo), each 128x64 u32 = 8192 u32
__device__ __align__(16) unsigned g_wbf[8][8192];

// ======================= mma.sync / ldmatrix helpers =======================
__device__ __forceinline__ uint32_t smem_u32(const void* p) {
    uint32_t a;
    asm("{ .reg .u64 t; cvta.to.shared.u64 t, %1; cvt.u32.u64 %0, t; }" : "=r"(a) : "l"(p));
    return a;
}

__device__ __forceinline__ void ldsm_x4(uint32_t addr, uint32_t r[4]) {
    asm volatile("ldmatrix.sync.aligned.m8n8.x4.shared.b16 {%0,%1,%2,%3}, [%4];"
                 : "=r"(r[0]), "=r"(r[1]), "=r"(r[2]), "=r"(r[3]) : "r"(addr));
}
__device__ __forceinline__ void ldsm_x4t(uint32_t addr, uint32_t r[4]) {
    asm volatile("ldmatrix.sync.aligned.m8n8.x4.trans.shared.b16 {%0,%1,%2,%3}, [%4];"
                 : "=r"(r[0]), "=r"(r[1]), "=r"(r[2]), "=r"(r[3]) : "r"(addr));
}
__device__ __forceinline__ void mma16816(float c[4], const uint32_t a[4],
                                         uint32_t b0, uint32_t b1) {
    asm volatile(
        "mma.sync.aligned.m16n8k16.row.col.f32.bf16.bf16.f32 "
        "{%0,%1,%2,%3}, {%4,%5,%6,%7}, {%8,%9}, {%0,%1,%2,%3};"
        : "+f"(c[0]), "+f"(c[1]), "+f"(c[2]), "+f"(c[3])
        : "r"(a[0]), "r"(a[1]), "r"(a[2]), "r"(a[3]), "r"(b0), "r"(b1));
}

__device__ __forceinline__ void bsplit(float v, unsigned short& h, unsigned short& l) {
    __nv_bfloat16 hb = __float2bfloat16(v);
    float r = v - __bfloat162float(hb);
    __nv_bfloat16 lb = __float2bfloat16(r);
    h = __bfloat16_as_ushort(hb);
    l = __bfloat16_as_ushort(lb);
}

// ---------------------------------------------------------------------------
// Weight prep: W[k][n] fp32 -> hi/lo bf16, kept K-major [k][n] (u32 = 2 halves)
// ---------------------------------------------------------------------------
__global__ void k_convw(const float* __restrict__ W,
                        unsigned* __restrict__ hi, unsigned* __restrict__ lo)
{
    int idx = blockIdx.x * blockDim.x + threadIdx.x;   // 8192 = 128k * 64 n-pairs
    if (idx >= 8192) return;
    int k = idx >> 6;
    int n = (idx & 63) * 2;
    float v0 = W[(size_t)k * 128 + n];
    float v1 = W[(size_t)k * 128 + n + 1];
    unsigned short h0, l0, h1, l1;
    bsplit(v0, h0, l0);
    bsplit(v1, h1, l1);
    hi[idx] = ((unsigned)h1 << 16) | h0;
    lo[idx] = ((unsigned)l1 << 16) | l0;
}

// ---------------------------------------------------------------------------
// Tensor-core GEMM: C[M,128] = act( A'[M,128] @ W[128,128] + bias )
//   A'[m,k] = IN_TRANSFORM ? relu(dis[m]*A[m,k]) : A[m,k];  act = RELU_OUT?relu:id
// 256 threads / 8 warps; warp w owns rows w*16..w*16+15 (all 128 cols).
// SMEM tiles padded to stride 136 halves (272B) -> conflict-free ldmatrix.
// ---------------------------------------------------------------------------
#define ASTR 136
#define SM_AHI 0
#define SM_ALO (128 * ASTR)
#define SM_WHI (2 * 128 * ASTR)
#define SM_WLO (3 * 128 * ASTR)
#define SM_HALVES (4 * 128 * ASTR)
#define SM_BYTES  (SM_HALVES * 2)

template<int RELU_OUT, int IN_TRANSFORM>
__global__ __launch_bounds__(256, 1)
void k_gemm_mma(const float* __restrict__ A,
                const unsigned* __restrict__ whi, const unsigned* __restrict__ wlo,
                const float* __restrict__ bias, float* __restrict__ C,
                const float* __restrict__ dis, int M)
{
    extern __shared__ __nv_bfloat16 smh[];
    const uint32_t sb = smem_u32(smh);
    const int tid = threadIdx.x;
    const int wid = tid >> 5, lid = tid & 31;
    const int bm = blockIdx.x * 128;

    // ---- load W hi/lo into smem [k][n], padded rows ----
    for (int i = tid; i < 8192; i += 256) {            // i = k*64 + npair
        int k = i >> 6, np = i & 63;
        unsigned vh = __ldg(whi + i);
        unsigned vl = __ldg(wlo + i);
        *(unsigned*)(smh + SM_WHI + k * ASTR + np * 2) = vh;
        *(unsigned*)(smh + SM_WLO + k * ASTR + np * 2) = vl;
    }

    // ---- load A tile (128 rows x 128 cols fp32), transform, split ----
    for (int i = tid; i < 4096; i += 256) {            // 4096 float4
        int r = i >> 5, c4 = (i & 31) * 4;
        int grow = bm + r;
        float4 v = make_float4(0.f, 0.f, 0.f, 0.f);
        if (grow < M) {
            v = *(const float4*)(A + (size_t)grow * 128 + c4);
            if (IN_TRANSFORM) {
                float dv = dis[grow];
                v.x = fmaxf(v.x * dv, 0.f); v.y = fmaxf(v.y * dv, 0.f);
                v.z = fmaxf(v.z * dv, 0.f); v.w = fmaxf(v.w * dv, 0.f);
            }
        }
        unsigned short hx, lx, hy, ly, hz, lz, hw, lw;
        bsplit(v.x, hx, lx); bsplit(v.y, hy, ly);
        bsplit(v.z, hz, lz); bsplit(v.w, hw, lw);
        unsigned* ph = (unsigned*)(smh + SM_AHI + r * ASTR + c4);
        unsigned* pl = (unsigned*)(smh + SM_ALO + r * ASTR + c4);
        ph[0] = ((unsigned)hy << 16) | hx;
        ph[1] = ((unsigned)hw << 16) | hz;
        pl[0] = ((unsigned)ly << 16) | lx;
        pl[1] = ((unsigned)lw << 16) | lz;
    }
    __syncthreads();

    // ---- per-lane ldmatrix base addresses ----
    const int wr = wid * 16;
    const int sub = lid >> 3, l7 = lid & 7;
    // A x4: blocks (rows wr..+7 | wr+8..+15) x (k | k+8)
    const int a_row = wr + (sub & 1) * 8 + l7;
    const int a_koff = (sub >> 1) * 8;
    const uint32_t aAddrHi = sb + (uint32_t)(SM_AHI + a_row * ASTR + a_koff) * 2u;
    const uint32_t aAddrLo = sb + (uint32_t)(SM_ALO + a_row * ASTR + a_koff) * 2u;
    // B x4.trans: blocks (k..k+7 | k+8..k+15) x (n | n+8)
    const int b_krow = (sub & 1) * 8 + l7;
    const int b_noff = (sub >> 1) * 8;
    const uint32_t bAddrHi = sb + (uint32_t)(SM_WHI + b_krow * ASTR + b_noff) * 2u;
    const uint32_t bAddrLo = sb + (uint32_t)(SM_WLO + b_krow * ASTR + b_noff) * 2u;

    float acc[16][4];
#pragma unroll
    for (int i = 0; i < 16; i++)
#pragma unroll
        for (int j = 0; j < 4; j++) acc[i][j] = 0.0f;

#pragma unroll
    for (int ks = 0; ks < 8; ks++) {
        const uint32_t kb = (uint32_t)(ks * 16) * 2u;                 // bytes
        uint32_t ah[4], al[4];
        ldsm_x4(aAddrHi + kb, ah);
        ldsm_x4(aAddrLo + kb, al);
        const uint32_t kRowB = (uint32_t)(ks * 16 * ASTR) * 2u;       // bytes
#pragma unroll
        for (int nb = 0; nb < 8; nb++) {
            uint32_t bh[4], bl[4];
            const uint32_t nOff = (uint32_t)(nb * 16) * 2u;
            ldsm_x4t(bAddrHi + kRowB + nOff, bh);
            ldsm_x4t(bAddrLo + kRowB + nOff, bl);
            mma16816(acc[nb * 2],     ah, bh[0], bh[1]);
            mma16816(acc[nb * 2 + 1], ah, bh[2], bh[3]);
            mma16816(acc[nb * 2],     ah, bl[0], bl[1]);
            mma16816(acc[nb * 2 + 1], ah, bl[2], bl[3]);
            mma16816(acc[nb * 2],     al, bh[0], bh[1]);
            mma16816(acc[nb * 2 + 1], al, bh[2], bh[3]);
        }
    }

    // ---- epilogue: c0,c1 -> row wr+gid, cols nb*8+tig*2; c2,c3 -> row wr+8+gid
    const int gid = lid >> 2, tig = lid & 3;
    const int row0 = bm + wr + gid;
    const int row1 = row0 + 8;
#pragma unroll
    for (int nb = 0; nb < 16; nb++) {
        int col = nb * 8 + tig * 2;
        float2 bv = *(const float2*)(bias + col);
        if (row0 < M) {
            float2 o;
            o.x = acc[nb][0] + bv.x;
            o.y = acc[nb][1] + bv.y;
            if (RELU_OUT) { o.x = fmaxf(o.x, 0.f); o.y = fmaxf(o.y, 0.f); }
            *(float2*)(C + (size_t)row0 * 128 + col) = o;
        }
        if (row1 < M) {
            float2 o;
            o.x = acc[nb][2] + bv.x;
            o.y = acc[nb][3] + bv.y;
            if (RELU_OUT) { o.x = fmaxf(o.x, 0.f); o.y = fmaxf(o.y, 0.f); }
            *(float2*)(C + (size_t)row1 * 128 + col) = o;
        }
    }
}

// ---------------------------------------------------------------------------
// CSR build kernels
// ---------------------------------------------------------------------------
__global__ void k_deg(const int* __restrict__ ei, int E, int* __restrict__ deg)
{
    int e = blockIdx.x * blockDim.x + threadIdx.x;
    if (e < E) atomicAdd(&deg[ei[e]], 1);
}

__global__ void k_dis(const int* __restrict__ deg, float* __restrict__ dis, int n)
{
    int i = blockIdx.x * blockDim.x + threadIdx.x;
    if (i < n) {
        int d = deg[i];
        dis[i] = (d > 0) ? rsqrtf((float)d) : 0.0f;
    }
}

__global__ void k_scan(const int* __restrict__ deg, int* __restrict__ offs, int n)
{
    __shared__ int sm[1024];
    __shared__ int carry;
    if (threadIdx.x == 0) carry = 0;
    __syncthreads();
    for (int base = 0; base < n; base += 1024) {
        int i = base + threadIdx.x;
        int v = (i < n) ? deg[i] : 0;
        sm[threadIdx.x] = v;
        __syncthreads();
        for (int off = 1; off < 1024; off <<= 1) {
            int t = (threadIdx.x >= off) ? sm[threadIdx.x - off] : 0;
            __syncthreads();
            sm[threadIdx.x] += t;
            __syncthreads();
        }
        if (i < n) offs[i + 1] = carry + sm[threadIdx.x];
        __syncthreads();
        if (threadIdx.x == 1023) carry += sm[1023];
        __syncthreads();
    }
    if (threadIdx.x == 0) offs[0] = 0;
}

__global__ void k_scatter(const int* __restrict__ ei, int E,
                          const int* __restrict__ offs, int* __restrict__ cursor,
                          int* __restrict__ cols)
{
    int e = blockIdx.x * blockDim.x + threadIdx.x;
    if (e >= E) return;
    int r = ei[e];
    int c = ei[E + e];
    int pos = offs[r] + atomicAdd(&cursor[r], 1);
    cols[pos] = c;
}

// ---------------------------------------------------------------------------
// CSR aggregation: agg[n,:] = sum_{c in nbrs(n)} dis[c] * h[c,:]
// ---------------------------------------------------------------------------
__global__ void k_aggregate(const float* __restrict__ h,
                            const int* __restrict__ offs,
                            const int* __restrict__ cols,
                            const float* __restrict__ dis,
                            float* __restrict__ agg, int n)
{
    int warp = (blockIdx.x * blockDim.x + threadIdx.x) >> 5;
    int lane = threadIdx.x & 31;
    if (warp >= n) return;
    int s = offs[warp], e = offs[warp + 1];
    float4 acc = make_float4(0.f, 0.f, 0.f, 0.f);
    for (int i = s; i < e; i++) {
        int c = __ldg(cols + i);
        float nr = __ldg(dis + c);
        float4 v = *reinterpret_cast<const float4*>(h + (size_t)c * 128 + lane * 4);
        acc.x = fmaf(nr, v.x, acc.x);
        acc.y = fmaf(nr, v.y, acc.y);
        acc.z = fmaf(nr, v.z, acc.z);
        acc.w = fmaf(nr, v.w, acc.w);
    }
    *reinterpret_cast<float4*>(agg + (size_t)warp * 128 + lane * 4) = acc;
}

// ---------------------------------------------------------------------------
// pooling: gsum[col] += sum_n relu(dis[n] * agg[n,col])
// ---------------------------------------------------------------------------
__global__ void k_pool(const float* __restrict__ agg, const float* __restrict__ dis,
                       float* __restrict__ gsum, int n)
{
    int col = threadIdx.x & 127;
    int sub = threadIdx.x >> 7;
    float acc = 0.0f;
    for (int row = blockIdx.x * 2 + sub; row < n; row += gridDim.x * 2) {
        float d = dis[row];
        float v = d * agg[(size_t)row * 128 + col];
        acc += fmaxf(v, 0.f);
    }
    __shared__ float sm[256];
    sm[threadIdx.x] = acc;
    __syncthreads();
    if (threadIdx.x < 128)
        atomicAdd(&gsum[col], sm[threadIdx.x] + sm[threadIdx.x + 128]);
}

// ---------------------------------------------------------------------------
// final MLP
// ---------------------------------------------------------------------------
__global__ void k_final(const float* __restrict__ gsum,
                        const float* __restrict__ w1, const float* __restrict__ b1,
                        const float* __restrict__ w2, const float* __restrict__ b2,
                        float* __restrict__ out, float invN)
{
    __shared__ float cv[512];
    __shared__ float red[128];
    int t = threadIdx.x;
    float a = gsum[t] * invN;
    float b = gsum[128 + t] * invN;
    cv[t]       = a;
    cv[128 + t] = b;
    cv[256 + t] = fabsf(a - b);
    cv[384 + t] = a * b;
    __syncthreads();
    float acc = b1[t];
    for (int k = 0; k < 512; k++)
        acc = fmaf(cv[k], w1[k * 128 + t], acc);
    acc = fmaxf(acc, 0.f);
    red[t] = acc * w2[t];
    __syncthreads();
    for (int s = 64; s > 0; s >>= 1) {
        if (t < s) red[t] += red[t + s];
        __syncthreads();
    }
    if (t == 0) out[0] = red[0] + b2[0];
}

// ---------------------------------------------------------------------------
// launch
// ---------------------------------------------------------------------------
extern "C" void kernel_launch(void* const* d_in, const int* in_sizes, int n_in,
                              void* d_out, int out_size)
{
    const float* x1  = (const float*)d_in[0];
    const int*   ei1 = (const int*)d_in[1];
    const float* x2  = (const float*)d_in[2];
    const int*   ei2 = (const int*)d_in[3];
    const float* enc_w1 = (const float*)d_in[4];
    const float* enc_b1 = (const float*)d_in[5];
    const float* enc_w2 = (const float*)d_in[6];
    const float* enc_b2 = (const float*)d_in[7];
    const float* conv1_w = (const float*)d_in[8];
    const float* conv1_b = (const float*)d_in[9];
    const float* conv2_w = (const float*)d_in[10];
    const float* conv2_b = (const float*)d_in[11];
    const float* sim_w1 = (const float*)d_in[12];
    const float* sim_b1 = (const float*)d_in[13];
    const float* sim_w2 = (const float*)d_in[14];
    const float* sim_b2 = (const float*)d_in[15];

    const int n = in_sizes[0] / HDIM;
    const int E = in_sizes[1] / 2;

    float *bufA, *bufB, *dis, *gsum;
    int *deg, *offs, *cursor, *csr_col;
    unsigned* wbf;
    cudaGetSymbolAddress((void**)&bufA,    g_bufA);
    cudaGetSymbolAddress((void**)&bufB,    g_bufB);
    cudaGetSymbolAddress((void**)&deg,     g_deg);
    cudaGetSymbolAddress((void**)&dis,     g_dis);
    cudaGetSymbolAddress((void**)&offs,    g_offs);
    cudaGetSymbolAddress((void**)&cursor,  g_cursor);
    cudaGetSymbolAddress((void**)&csr_col, g_csr_col);
    cudaGetSymbolAddress((void**)&gsum,    g_gsum);
    cudaGetSymbolAddress((void**)&wbf,     g_wbf);

    cudaFuncSetAttribute(k_gemm_mma<1, 0>, cudaFuncAttributeMaxDynamicSharedMemorySize, SM_BYTES);
    cudaFuncSetAttribute(k_gemm_mma<0, 0>, cudaFuncAttributeMaxDynamicSharedMemorySize, SM_BYTES);
    cudaFuncSetAttribute(k_gemm_mma<0, 1>, cudaFuncAttributeMaxDynamicSharedMemorySize, SM_BYTES);

    const int gemmBlocks = (n + 127) / 128;
    const int eBlocks    = (E + 255) / 256;
    const int nBlocks    = (n + 255) / 256;
    const int aggBlocks  = (n * 32 + 255) / 256;

    cudaMemsetAsync(gsum, 0, 2 * HDIM * sizeof(float));

    // weight prep (shared across both graphs); image stride = 8192 u32
    k_convw<<<32, 256>>>(enc_w1,  wbf + 0 * 8192, wbf + 1 * 8192);
    k_convw<<<32, 256>>>(enc_w2,  wbf + 2 * 8192, wbf + 3 * 8192);
    k_convw<<<32, 256>>>(conv1_w, wbf + 4 * 8192, wbf + 5 * 8192);
    k_convw<<<32, 256>>>(conv2_w, wbf + 6 * 8192, wbf + 7 * 8192);

    for (int g = 0; g < 2; g++) {
        const float* x  = (g == 0) ? x1 : x2;
        const int*   ei = (g == 0) ? ei1 : ei2;

        // --- CSR build (shared by both GCN layers) ---
        cudaMemsetAsync(deg, 0, n * sizeof(int));
        cudaMemsetAsync(cursor, 0, n * sizeof(int));
        k_deg<<<eBlocks, 256>>>(ei, E, deg);
        k_dis<<<nBlocks, 256>>>(deg, dis, n);
        k_scan<<<1, 1024>>>(deg, offs, n);
        k_scatter<<<eBlocks, 256>>>(ei, E, offs, cursor, csr_col);

        // --- encoder MLP ---
        k_gemm_mma<1, 0><<<gemmBlocks, 256, SM_BYTES>>>(x,    wbf + 0 * 8192, wbf + 1 * 8192, enc_b1, bufA, dis, n);
        k_gemm_mma<0, 0><<<gemmBlocks, 256, SM_BYTES>>>(bufA, wbf + 2 * 8192, wbf + 3 * 8192, enc_b2, bufB, dis, n);

        // --- GCN layer 1 ---
        k_gemm_mma<0, 0><<<gemmBlocks, 256, SM_BYTES>>>(bufB, wbf + 4 * 8192, wbf + 5 * 8192, conv1_b, bufA, dis, n);
        k_aggregate<<<aggBlocks, 256>>>(bufA, offs, csr_col, dis, bufB, n);

        // --- GCN layer 2 (input transform relu(dis*agg) fused) ---
        k_gemm_mma<0, 1><<<gemmBlocks, 256, SM_BYTES>>>(bufB, wbf + 6 * 8192, wbf + 7 * 8192, conv2_b, bufA, dis, n);
        k_aggregate<<<aggBlocks, 256>>>(bufA, offs, csr_col, dis, bufB, n);

        // --- mean pool ---
        k_pool<<<256, 256>>>(bufB, dis, gsum + g * HDIM, n);
    }

    k_final<<<1, 128>>>(gsum, sim_w1, sim_b1, sim_w2, sim_b2,
                        (float*)d_out, 1.0f / (float)n);
}

// round 5
// speedup vs baseline: 1.5690x; 1.2480x over previous
#include <cuda_runtime.h>
#include <cuda_bf16.h>
#include <math.h>
#include <stdint.h>

// ---------------------------------------------------------------------------
// GraphSimilarity: 2x { encoder MLP (2 GEMMs) -> GCN -> GCN -> mean pool }
//                  -> similarity MLP -> scalar
// GEMMs on mma.sync (bf16 3-term split, fp32 acc). CSR built without a scan
// (unordered row-chunk assignment). Layer-2 aggregate fused with mean-pool.
// ---------------------------------------------------------------------------

#define MAXN 50000
#define MAXE 800000
#define HDIM 128

__device__ __align__(16) float g_bufA[MAXN * HDIM];
__device__ __align__(16) float g_bufB[MAXN * HDIM];
// int scratch: [0,MAXN) deg | [MAXN,2*MAXN) cursor | [2*MAXN] gctr
__device__ int   g_icsr[2 * MAXN + 1];
__device__ float g_dis[MAXN];
__device__ int   g_offs[MAXN];
__device__ int   g_csr_col[MAXE];
__device__ float g_gsum[2 * HDIM];
// bf16 weight splits: 8 images (4 weights x hi/lo), each 128x64 u32 = 8192 u32
__device__ __align__(16) unsigned g_wbf[8][8192];

// ======================= mma.sync / ldmatrix helpers =======================
__device__ __forceinline__ uint32_t smem_u32(const void* p) {
    uint32_t a;
    asm("{ .reg .u64 t; cvta.to.shared.u64 t, %1; cvt.u32.u64 %0, t; }" : "=r"(a) : "l"(p));
    return a;
}

__device__ __forceinline__ void ldsm_x4(uint32_t addr, uint32_t r[4]) {
    asm volatile("ldmatrix.sync.aligned.m8n8.x4.shared.b16 {%0,%1,%2,%3}, [%4];"
                 : "=r"(r[0]), "=r"(r[1]), "=r"(r[2]), "=r"(r[3]) : "r"(addr));
}
__device__ __forceinline__ void ldsm_x4t(uint32_t addr, uint32_t r[4]) {
    asm volatile("ldmatrix.sync.aligned.m8n8.x4.trans.shared.b16 {%0,%1,%2,%3}, [%4];"
                 : "=r"(r[0]), "=r"(r[1]), "=r"(r[2]), "=r"(r[3]) : "r"(addr));
}
__device__ __forceinline__ void mma16816(float c[4], const uint32_t a[4],
                                         uint32_t b0, uint32_t b1) {
    asm volatile(
        "mma.sync.aligned.m16n8k16.row.col.f32.bf16.bf16.f32 "
        "{%0,%1,%2,%3}, {%4,%5,%6,%7}, {%8,%9}, {%0,%1,%2,%3};"
        : "+f"(c[0]), "+f"(c[1]), "+f"(c[2]), "+f"(c[3])
        : "r"(a[0]), "r"(a[1]), "r"(a[2]), "r"(a[3]), "r"(b0), "r"(b1));
}

__device__ __forceinline__ void bsplit(float v, unsigned short& h, unsigned short& l) {
    __nv_bfloat16 hb = __float2bfloat16(v);
    float r = v - __bfloat162float(hb);
    __nv_bfloat16 lb = __float2bfloat16(r);
    h = __bfloat16_as_ushort(hb);
    l = __bfloat16_as_ushort(lb);
}

// ---------------------------------------------------------------------------
// Weight prep: all 4 weights in one launch (grid.y selects weight).
// W[k][n] fp32 -> hi/lo bf16, K-major [k][n] (u32 = 2 halves).
// ---------------------------------------------------------------------------
__global__ void k_convw(const float* __restrict__ w0, const float* __restrict__ w1,
                        const float* __restrict__ w2, const float* __restrict__ w3,
                        unsigned* __restrict__ wbf)
{
    int idx = blockIdx.x * blockDim.x + threadIdx.x;   // 8192 = 128k * 64 n-pairs
    if (idx >= 8192) return;
    const float* W = (blockIdx.y == 0) ? w0 : (blockIdx.y == 1) ? w1
                   : (blockIdx.y == 2) ? w2 : w3;
    unsigned* hi = wbf + (size_t)(2 * blockIdx.y) * 8192;
    unsigned* lo = hi + 8192;
    int k = idx >> 6;
    int n = (idx & 63) * 2;
    float v0 = W[(size_t)k * 128 + n];
    float v1 = W[(size_t)k * 128 + n + 1];
    unsigned short h0, l0, h1, l1;
    bsplit(v0, h0, l0);
    bsplit(v1, h1, l1);
    hi[idx] = ((unsigned)h1 << 16) | h0;
    lo[idx] = ((unsigned)l1 << 16) | l0;
}

// ---------------------------------------------------------------------------
// Tensor-core GEMM: C[M,128] = act( A'[M,128] @ W[128,128] + bias )
//   A'[m,k] = IN_TRANSFORM ? relu(dis[m]*A[m,k]) : A[m,k];  act = RELU_OUT?relu:id
// 256 threads / 8 warps; warp w owns rows w*16..w*16+15 (all 128 cols).
// SMEM tiles padded to stride 136 halves (272B) -> conflict-free ldmatrix.
// ---------------------------------------------------------------------------
#define ASTR 136
#define SM_AHI 0
#define SM_ALO (128 * ASTR)
#define SM_WHI (2 * 128 * ASTR)
#define SM_WLO (3 * 128 * ASTR)
#define SM_HALVES (4 * 128 * ASTR)
#define SM_BYTES  (SM_HALVES * 2)

template<int RELU_OUT, int IN_TRANSFORM>
__global__ __launch_bounds__(256, 1)
void k_gemm_mma(const float* __restrict__ A,
                const unsigned* __restrict__ whi, const unsigned* __restrict__ wlo,
                const float* __restrict__ bias, float* __restrict__ C,
                const float* __restrict__ dis, int M)
{
    extern __shared__ __nv_bfloat16 smh[];
    const uint32_t sb = smem_u32(smh);
    const int tid = threadIdx.x;
    const int wid = tid >> 5, lid = tid & 31;
    const int bm = blockIdx.x * 128;

    // ---- load W hi/lo into smem [k][n], padded rows ----
    for (int i = tid; i < 8192; i += 256) {            // i = k*64 + npair
        int k = i >> 6, np = i & 63;
        unsigned vh = __ldg(whi + i);
        unsigned vl = __ldg(wlo + i);
        *(unsigned*)(smh + SM_WHI + k * ASTR + np * 2) = vh;
        *(unsigned*)(smh + SM_WLO + k * ASTR + np * 2) = vl;
    }

    // ---- load A tile (128 rows x 128 cols fp32), transform, split ----
    for (int i = tid; i < 4096; i += 256) {            // 4096 float4
        int r = i >> 5, c4 = (i & 31) * 4;
        int grow = bm + r;
        float4 v = make_float4(0.f, 0.f, 0.f, 0.f);
        if (grow < M) {
            v = *(const float4*)(A + (size_t)grow * 128 + c4);
            if (IN_TRANSFORM) {
                float dv = dis[grow];
                v.x = fmaxf(v.x * dv, 0.f); v.y = fmaxf(v.y * dv, 0.f);
                v.z = fmaxf(v.z * dv, 0.f); v.w = fmaxf(v.w * dv, 0.f);
            }
        }
        unsigned short hx, lx, hy, ly, hz, lz, hw, lw;
        bsplit(v.x, hx, lx); bsplit(v.y, hy, ly);
        bsplit(v.z, hz, lz); bsplit(v.w, hw, lw);
        unsigned* ph = (unsigned*)(smh + SM_AHI + r * ASTR + c4);
        unsigned* pl = (unsigned*)(smh + SM_ALO + r * ASTR + c4);
        ph[0] = ((unsigned)hy << 16) | hx;
        ph[1] = ((unsigned)hw << 16) | hz;
        pl[0] = ((unsigned)ly << 16) | lx;
        pl[1] = ((unsigned)lw << 16) | lz;
    }
    __syncthreads();

    // ---- per-lane ldmatrix base addresses ----
    const int wr = wid * 16;
    const int sub = lid >> 3, l7 = lid & 7;
    const int a_row = wr + (sub & 1) * 8 + l7;
    const int a_koff = (sub >> 1) * 8;
    const uint32_t aAddrHi = sb + (uint32_t)(SM_AHI + a_row * ASTR + a_koff) * 2u;
    const uint32_t aAddrLo = sb + (uint32_t)(SM_ALO + a_row * ASTR + a_koff) * 2u;
    const int b_krow = (sub & 1) * 8 + l7;
    const int b_noff = (sub >> 1) * 8;
    const uint32_t bAddrHi = sb + (uint32_t)(SM_WHI + b_krow * ASTR + b_noff) * 2u;
    const uint32_t bAddrLo = sb + (uint32_t)(SM_WLO + b_krow * ASTR + b_noff) * 2u;

    float acc[16][4];
#pragma unroll
    for (int i = 0; i < 16; i++)
#pragma unroll
        for (int j = 0; j < 4; j++) acc[i][j] = 0.0f;

#pragma unroll
    for (int ks = 0; ks < 8; ks++) {
        const uint32_t kb = (uint32_t)(ks * 16) * 2u;
        uint32_t ah[4], al[4];
        ldsm_x4(aAddrHi + kb, ah);
        ldsm_x4(aAddrLo + kb, al);
        const uint32_t kRowB = (uint32_t)(ks * 16 * ASTR) * 2u;
#pragma unroll
        for (int nb = 0; nb < 8; nb++) {
            uint32_t bh[4], bl[4];
            const uint32_t nOff = (uint32_t)(nb * 16) * 2u;
            ldsm_x4t(bAddrHi + kRowB + nOff, bh);
            ldsm_x4t(bAddrLo + kRowB + nOff, bl);
            mma16816(acc[nb * 2],     ah, bh[0], bh[1]);
            mma16816(acc[nb * 2 + 1], ah, bh[2], bh[3]);
            mma16816(acc[nb * 2],     ah, bl[0], bl[1]);
            mma16816(acc[nb * 2 + 1], ah, bl[2], bl[3]);
            mma16816(acc[nb * 2],     al, bh[0], bh[1]);
            mma16816(acc[nb * 2 + 1], al, bh[2], bh[3]);
        }
    }

    const int gid = lid >> 2, tig = lid & 3;
    const int row0 = bm + wr + gid;
    const int row1 = row0 + 8;
#pragma unroll
    for (int nb = 0; nb < 16; nb++) {
        int col = nb * 8 + tig * 2;
        float2 bv = *(const float2*)(bias + col);
        if (row0 < M) {
            float2 o;
            o.x = acc[nb][0] + bv.x;
            o.y = acc[nb][1] + bv.y;
            if (RELU_OUT) { o.x = fmaxf(o.x, 0.f); o.y = fmaxf(o.y, 0.f); }
            *(float2*)(C + (size_t)row0 * 128 + col) = o;
        }
        if (row1 < M) {
            float2 o;
            o.x = acc[nb][2] + bv.x;
            o.y = acc[nb][3] + bv.y;
            if (RELU_OUT) { o.x = fmaxf(o.x, 0.f); o.y = fmaxf(o.y, 0.f); }
            *(float2*)(C + (size_t)row1 * 128 + col) = o;
        }
    }
}

// ---------------------------------------------------------------------------
// CSR build
// ---------------------------------------------------------------------------
__global__ void k_deg(const int* __restrict__ ei, int E, int* __restrict__ deg)
{
    int e = blockIdx.x * blockDim.x + threadIdx.x;
    if (e < E) atomicAdd(&deg[ei[e]], 1);
}

// dis + unordered CSR row-chunk assignment (no scan needed: row order in the
// CSR is irrelevant, each row just needs a private contiguous slot range).
__global__ void k_dis_offs(const int* __restrict__ deg, float* __restrict__ dis,
                           int* __restrict__ offs, int* __restrict__ gctr, int n)
{
    int i = blockIdx.x * blockDim.x + threadIdx.x;
    if (i < n) {
        int d = deg[i];
        dis[i] = (d > 0) ? rsqrtf((float)d) : 0.0f;
        offs[i] = atomicAdd(gctr, d);
    }
}

__global__ void k_scatter(const int* __restrict__ ei, int E,
                          const int* __restrict__ offs, int* __restrict__ cursor,
                          int* __restrict__ cols)
{
    int e = blockIdx.x * blockDim.x + threadIdx.x;
    if (e >= E) return;
    int r = ei[e];
    int c = ei[E + e];
    int pos = offs[r] + atomicAdd(&cursor[r], 1);
    cols[pos] = c;
}

// ---------------------------------------------------------------------------
// CSR aggregation: agg[n,:] = sum_{c in nbrs(n)} dis[c] * h[c,:]
// One warp per node, 2-way unroll (2 independent 512B row loads in flight).
// ---------------------------------------------------------------------------
__global__ void k_aggregate(const float* __restrict__ h,
                            const int* __restrict__ offs, const int* __restrict__ deg,
                            const int* __restrict__ cols,
                            const float* __restrict__ dis,
                            float* __restrict__ agg, int n)
{
    int warp = (blockIdx.x * blockDim.x + threadIdx.x) >> 5;
    int lane = threadIdx.x & 31;
    if (warp >= n) return;
    int s = __ldg(offs + warp);
    int e = s + __ldg(deg + warp);
    float4 a0 = make_float4(0.f, 0.f, 0.f, 0.f);
    float4 a1 = make_float4(0.f, 0.f, 0.f, 0.f);
    int i = s;
    for (; i + 2 <= e; i += 2) {
        int c0 = __ldg(cols + i), c1 = __ldg(cols + i + 1);
        float n0 = __ldg(dis + c0), n1 = __ldg(dis + c1);
        float4 v0 = *(const float4*)(h + (size_t)c0 * 128 + lane * 4);
        float4 v1 = *(const float4*)(h + (size_t)c1 * 128 + lane * 4);
        a0.x = fmaf(n0, v0.x, a0.x); a0.y = fmaf(n0, v0.y, a0.y);
        a0.z = fmaf(n0, v0.z, a0.z); a0.w = fmaf(n0, v0.w, a0.w);
        a1.x = fmaf(n1, v1.x, a1.x); a1.y = fmaf(n1, v1.y, a1.y);
        a1.z = fmaf(n1, v1.z, a1.z); a1.w = fmaf(n1, v1.w, a1.w);
    }
    if (i < e) {
        int c0 = __ldg(cols + i);
        float n0 = __ldg(dis + c0);
        float4 v0 = *(const float4*)(h + (size_t)c0 * 128 + lane * 4);
        a0.x = fmaf(n0, v0.x, a0.x); a0.y = fmaf(n0, v0.y, a0.y);
        a0.z = fmaf(n0, v0.z, a0.z); a0.w = fmaf(n0, v0.w, a0.w);
    }
    a0.x += a1.x; a0.y += a1.y; a0.z += a1.z; a0.w += a1.w;
    *(float4*)(agg + (size_t)warp * 128 + lane * 4) = a0;
}

// ---------------------------------------------------------------------------
// Fused aggregate + mean-pool (layer 2): gsum[col] += relu(dis[row]*acc[col])
// summed over rows; per-block smem partial, one global atomic per col/block.
// ---------------------------------------------------------------------------
__global__ void k_aggpool(const float* __restrict__ h,
                          const int* __restrict__ offs, const int* __restrict__ deg,
                          const int* __restrict__ cols,
                          const float* __restrict__ dis,
                          float* __restrict__ gsum, int n)
{
    __shared__ float gpart[128];
    if (threadIdx.x < 128) gpart[threadIdx.x] = 0.0f;
    __syncthreads();

    int warp = (blockIdx.x * blockDim.x + threadIdx.x) >> 5;
    int lane = threadIdx.x & 31;
    if (warp < n) {
        int s = __ldg(offs + warp);
        int e = s + __ldg(deg + warp);
        float4 a0 = make_float4(0.f, 0.f, 0.f, 0.f);
        float4 a1 = make_float4(0.f, 0.f, 0.f, 0.f);
        int i = s;
        for (; i + 2 <= e; i += 2) {
            int c0 = __ldg(cols + i), c1 = __ldg(cols + i + 1);
            float n0 = __ldg(dis + c0), n1 = __ldg(dis + c1);
            float4 v0 = *(const float4*)(h + (size_t)c0 * 128 + lane * 4);
            float4 v1 = *(const float4*)(h + (size_t)c1 * 128 + lane * 4);
            a0.x = fmaf(n0, v0.x, a0.x); a0.y = fmaf(n0, v0.y, a0.y);
            a0.z = fmaf(n0, v0.z, a0.z); a0.w = fmaf(n0, v0.w, a0.w);
            a1.x = fmaf(n1, v1.x, a1.x); a1.y = fmaf(n1, v1.y, a1.y);
            a1.z = fmaf(n1, v1.z, a1.z); a1.w = fmaf(n1, v1.w, a1.w);
        }
        if (i < e) {
            int c0 = __ldg(cols + i);
            float n0 = __ldg(dis + c0);
            float4 v0 = *(const float4*)(h + (size_t)c0 * 128 + lane * 4);
            a0.x = fmaf(n0, v0.x, a0.x); a0.y = fmaf(n0, v0.y, a0.y);
            a0.z = fmaf(n0, v0.z, a0.z); a0.w = fmaf(n0, v0.w, a0.w);
        }
        float d = __ldg(dis + warp);
        float rx = fmaxf(d * (a0.x + a1.x), 0.f);
        float ry = fmaxf(d * (a0.y + a1.y), 0.f);
        float rz = fmaxf(d * (a0.z + a1.z), 0.f);
        float rw = fmaxf(d * (a0.w + a1.w), 0.f);
        atomicAdd(&gpart[lane * 4 + 0], rx);
        atomicAdd(&gpart[lane * 4 + 1], ry);
        atomicAdd(&gpart[lane * 4 + 2], rz);
        atomicAdd(&gpart[lane * 4 + 3], rw);
    }
    __syncthreads();
    if (threadIdx.x < 128) {
        float v = gpart[threadIdx.x];
        if (v != 0.0f) atomicAdd(&gsum[threadIdx.x], v);
    }
}

// ---------------------------------------------------------------------------
// final MLP
// ---------------------------------------------------------------------------
__global__ void k_final(const float* __restrict__ gsum,
                        const float* __restrict__ w1, const float* __restrict__ b1,
                        const float* __restrict__ w2, const float* __restrict__ b2,
                        float* __restrict__ out, float invN)
{
    __shared__ float cv[512];
    __shared__ float red[128];
    int t = threadIdx.x;
    float a = gsum[t] * invN;
    float b = gsum[128 + t] * invN;
    cv[t]       = a;
    cv[128 + t] = b;
    cv[256 + t] = fabsf(a - b);
    cv[384 + t] = a * b;
    __syncthreads();
    float acc = b1[t];
    for (int k = 0; k < 512; k++)
        acc = fmaf(cv[k], w1[k * 128 + t], acc);
    acc = fmaxf(acc, 0.f);
    red[t] = acc * w2[t];
    __syncthreads();
    for (int s = 64; s > 0; s >>= 1) {
        if (t < s) red[t] += red[t + s];
        __syncthreads();
    }
    if (t == 0) out[0] = red[0] + b2[0];
}

// ---------------------------------------------------------------------------
// launch
// ---------------------------------------------------------------------------
extern "C" void kernel_launch(void* const* d_in, const int* in_sizes, int n_in,
                              void* d_out, int out_size)
{
    const float* x1  = (const float*)d_in[0];
    const int*   ei1 = (const int*)d_in[1];
    const float* x2  = (const float*)d_in[2];
    const int*   ei2 = (const int*)d_in[3];
    const float* enc_w1 = (const float*)d_in[4];
    const float* enc_b1 = (const float*)d_in[5];
    const float* enc_w2 = (const float*)d_in[6];
    const float* enc_b2 = (const float*)d_in[7];
    const float* conv1_w = (const float*)d_in[8];
    const float* conv1_b = (const float*)d_in[9];
    const float* conv2_w = (const float*)d_in[10];
    const float* conv2_b = (const float*)d_in[11];
    const float* sim_w1 = (const float*)d_in[12];
    const float* sim_b1 = (const float*)d_in[13];
    const float* sim_w2 = (const float*)d_in[14];
    const float* sim_b2 = (const float*)d_in[15];

    const int n = in_sizes[0] / HDIM;
    const int E = in_sizes[1] / 2;

    float *bufA, *bufB, *dis, *gsum;
    int *icsr, *offs, *csr_col;
    unsigned* wbf;
    cudaGetSymbolAddress((void**)&bufA,    g_bufA);
    cudaGetSymbolAddress((void**)&bufB,    g_bufB);
    cudaGetSymbolAddress((void**)&icsr,    g_icsr);
    cudaGetSymbolAddress((void**)&dis,     g_dis);
    cudaGetSymbolAddress((void**)&offs,    g_offs);
    cudaGetSymbolAddress((void**)&csr_col, g_csr_col);
    cudaGetSymbolAddress((void**)&gsum,    g_gsum);
    cudaGetSymbolAddress((void**)&wbf,     g_wbf);

    int* deg    = icsr;
    int* cursor = icsr + MAXN;
    int* gctr   = icsr + 2 * MAXN;

    cudaFuncSetAttribute(k_gemm_mma<1, 0>, cudaFuncAttributeMaxDynamicSharedMemorySize, SM_BYTES);
    cudaFuncSetAttribute(k_gemm_mma<0, 0>, cudaFuncAttributeMaxDynamicSharedMemorySize, SM_BYTES);
    cudaFuncSetAttribute(k_gemm_mma<0, 1>, cudaFuncAttributeMaxDynamicSharedMemorySize, SM_BYTES);

    const int gemmBlocks = (n + 127) / 128;
    const int eBlocks    = (E + 255) / 256;
    const int nBlocks    = (n + 255) / 256;
    const int aggBlocks  = (n * 32 + 255) / 256;

    cudaMemsetAsync(gsum, 0, 2 * HDIM * sizeof(float));

    // weight prep (shared across both graphs), single launch
    {
        dim3 grid(32, 4);
        k_convw<<<grid, 256>>>(enc_w1, enc_w2, conv1_w, conv2_w, wbf);
    }

    for (int g = 0; g < 2; g++) {
        const float* x  = (g == 0) ? x1 : x2;
        const int*   ei = (g == 0) ? ei1 : ei2;

        // --- CSR build (deg+cursor+gctr zeroed in one memset) ---
        cudaMemsetAsync(icsr, 0, (2 * MAXN + 1) * sizeof(int));
        k_deg<<<eBlocks, 256>>>(ei, E, deg);
        k_dis_offs<<<nBlocks, 256>>>(deg, dis, offs, gctr, n);
        k_scatter<<<eBlocks, 256>>>(ei, E, offs, cursor, csr_col);

        // --- encoder MLP ---
        k_gemm_mma<1, 0><<<gemmBlocks, 256, SM_BYTES>>>(x,    wbf + 0 * 8192, wbf + 1 * 8192, enc_b1, bufA, dis, n);
        k_gemm_mma<0, 0><<<gemmBlocks, 256, SM_BYTES>>>(bufA, wbf + 2 * 8192, wbf + 3 * 8192, enc_b2, bufB, dis, n);

        // --- GCN layer 1 ---
        k_gemm_mma<0, 0><<<gemmBlocks, 256, SM_BYTES>>>(bufB, wbf + 4 * 8192, wbf + 5 * 8192, conv1_b, bufA, dis, n);
        k_aggregate<<<aggBlocks, 256>>>(bufA, offs, deg, csr_col, dis, bufB, n);

        // --- GCN layer 2 (relu(dis*agg) fused into GEMM; pool fused into agg) ---
        k_gemm_mma<0, 1><<<gemmBlocks, 256, SM_BYTES>>>(bufB, wbf + 6 * 8192, wbf + 7 * 8192, conv2_b, bufA, dis, n);
        k_aggpool<<<aggBlocks, 256>>>(bufA, offs, deg, csr_col, dis, gsum + g * HDIM, n);
    }

    k_final<<<1, 128>>>(gsum, sim_w1, sim_b1, sim_w2, sim_b2,
                        (float*)d_out, 1.0f / (float)n);
}

// round 8
// speedup vs baseline: 1.7322x; 1.1040x over previous
#include <cuda_runtime.h>
#include <cuda_bf16.h>
#include <math.h>
#include <stdint.h>

// ---------------------------------------------------------------------------
// GraphSimilarity: 2x { encoder MLP (2 GEMMs, FUSED) -> GCN -> GCN -> pool }
//                  -> similarity MLP -> scalar
// GEMMs on mma.sync (bf16 3-term split, fp32 acc). CSR built without a scan.
// Both graphs batched into every kernel launch (single stream, no events).
// ---------------------------------------------------------------------------

#define MAXN 50000
#define MAXE 800000
#define HDIM 128
#define ICSR (2 * MAXN + 1)

__device__ __align__(16) float g_bufA[2][MAXN * HDIM];
__device__ __align__(16) float g_bufB[2][MAXN * HDIM];
__device__ int   g_icsr[2][ICSR];     // deg | cursor | gctr
__device__ float g_dis[2][MAXN];
__device__ int   g_offs[2][MAXN];
__device__ int   g_csr_col[2][MAXE];
__device__ float g_gsum[2 * HDIM];
// bf16 weight splits: 8 images (w1hi,w1lo,w2hi,w2lo,c1hi,c1lo,c2hi,c2lo) x 8192 u32
__device__ __align__(16) unsigned g_wbf[8][8192];

// ======================= helpers ===========================================
__device__ __forceinline__ uint32_t smem_u32(const void* p) {
    uint32_t a;
    asm("{ .reg .u64 t; cvta.to.shared.u64 t, %1; cvt.u32.u64 %0, t; }" : "=r"(a) : "l"(p));
    return a;
}
__device__ __forceinline__ void ldsm_x4(uint32_t addr, uint32_t r[4]) {
    asm volatile("ldmatrix.sync.aligned.m8n8.x4.shared.b16 {%0,%1,%2,%3}, [%4];"
                 : "=r"(r[0]), "=r"(r[1]), "=r"(r[2]), "=r"(r[3]) : "r"(addr));
}
__device__ __forceinline__ void ldsm_x4t(uint32_t addr, uint32_t r[4]) {
    asm volatile("ldmatrix.sync.aligned.m8n8.x4.trans.shared.b16 {%0,%1,%2,%3}, [%4];"
                 : "=r"(r[0]), "=r"(r[1]), "=r"(r[2]), "=r"(r[3]) : "r"(addr));
}
__device__ __forceinline__ void mma16816(float c[4], const uint32_t a[4],
                                         uint32_t b0, uint32_t b1) {
    asm volatile(
        "mma.sync.aligned.m16n8k16.row.col.f32.bf16.bf16.f32 "
        "{%0,%1,%2,%3}, {%4,%5,%6,%7}, {%8,%9}, {%0,%1,%2,%3};"
        : "+f"(c[0]), "+f"(c[1]), "+f"(c[2]), "+f"(c[3])
        : "r"(a[0]), "r"(a[1]), "r"(a[2]), "r"(a[3]), "r"(b0), "r"(b1));
}
// packed rn split: hi/lo bf16 pairs for 2 fp32 values (low half = v0)
__device__ __forceinline__ void split2(float v0, float v1, unsigned& hi, unsigned& lo) {
    unsigned h;
    asm("cvt.rn.bf16x2.f32 %0, %1, %2;" : "=r"(h) : "f"(v1), "f"(v0));
    float f0 = __uint_as_float(h << 16);
    float f1 = __uint_as_float(h & 0xFFFF0000u);
    float r0 = v0 - f0, r1 = v1 - f1;
    unsigned l;
    asm("cvt.rn.bf16x2.f32 %0, %1, %2;" : "=r"(l) : "f"(r1), "f"(r0));
    hi = h; lo = l;
}

// ---------------------------------------------------------------------------
// Weight prep: 4 weights, one launch (grid.y selects weight).
// ---------------------------------------------------------------------------
__global__ void k_convw(const float* __restrict__ w0, const float* __restrict__ w1,
                        const float* __restrict__ w2, const float* __restrict__ w3,
                        unsigned* __restrict__ wbf)
{
    int idx = blockIdx.x * blockDim.x + threadIdx.x;   // 8192 = 128k * 64 n-pairs
    if (idx >= 8192) return;
    const float* W = (blockIdx.y == 0) ? w0 : (blockIdx.y == 1) ? w1
                   : (blockIdx.y == 2) ? w2 : w3;
    unsigned* hi = wbf + (size_t)(2 * blockIdx.y) * 8192;
    unsigned* lo = hi + 8192;
    int k = idx >> 6;
    int n = (idx & 63) * 2;
    unsigned h, l;
    split2(W[(size_t)k * 128 + n], W[(size_t)k * 128 + n + 1], h, l);
    hi[idx] = h;
    lo[idx] = l;
}

// ---------------------------------------------------------------------------
// GEMM building blocks
// ---------------------------------------------------------------------------
#define ASTR 136
#define TH   (128 * ASTR)          // halves per image
#define SM_AHI 0
#define SM_ALO TH
#define SM_BHI (2 * TH)
#define SM_BLO (3 * TH)
#define SM_B2HI (4 * TH)
#define SM_B2LO (5 * TH)
#define SM_BYTES   (4 * TH * 2)    // gcn gemm: A hi/lo + W hi/lo
#define SM6_BYTES  (6 * TH * 2)    // fused encoder: + W2 hi/lo

__device__ __forceinline__ void gemm_mainloop(uint32_t aHi, uint32_t aLo,
                                              uint32_t bHi, uint32_t bLo,
                                              float acc[16][4])
{
#pragma unroll
    for (int ks = 0; ks < 8; ks++) {
        const uint32_t kb = (uint32_t)(ks * 16) * 2u;
        uint32_t ah[4], al[4];
        ldsm_x4(aHi + kb, ah);
        ldsm_x4(aLo + kb, al);
        const uint32_t kRowB = (uint32_t)(ks * 16 * ASTR) * 2u;
#pragma unroll
        for (int nb = 0; nb < 8; nb++) {
            uint32_t bh[4], bl[4];
            const uint32_t nOff = (uint32_t)(nb * 16) * 2u;
            ldsm_x4t(bHi + kRowB + nOff, bh);
            ldsm_x4t(bLo + kRowB + nOff, bl);
            mma16816(acc[nb * 2],     ah, bh[0], bh[1]);
            mma16816(acc[nb * 2 + 1], ah, bh[2], bh[3]);
            mma16816(acc[nb * 2],     ah, bl[0], bl[1]);
            mma16816(acc[nb * 2 + 1], ah, bl[2], bl[3]);
            mma16816(acc[nb * 2],     al, bh[0], bh[1]);
            mma16816(acc[nb * 2 + 1], al, bh[2], bh[3]);
        }
    }
}

// A-tile load + split into smem (optional relu(dis*x) transform)
template<int IN_TRANSFORM>
__device__ __forceinline__ void load_a_tile(__nv_bfloat16* smh, const float* A,
                                            const float* dis, int bm, int M, int tid)
{
    for (int i = tid; i < 4096; i += 256) {            // 4096 float4
        int r = i >> 5, c4 = (i & 31) * 4;
        int grow = bm + r;
        float4 v = make_float4(0.f, 0.f, 0.f, 0.f);
        if (grow < M) {
            v = *(const float4*)(A + (size_t)grow * 128 + c4);
            if (IN_TRANSFORM) {
                float dv = dis[grow];
                v.x = fmaxf(v.x * dv, 0.f); v.y = fmaxf(v.y * dv, 0.f);
                v.z = fmaxf(v.z * dv, 0.f); v.w = fmaxf(v.w * dv, 0.f);
            }
        }
        unsigned h0, l0, h1, l1;
        split2(v.x, v.y, h0, l0);
        split2(v.z, v.w, h1, l1);
        unsigned* ph = (unsigned*)(smh + SM_AHI + r * ASTR + c4);
        unsigned* pl = (unsigned*)(smh + SM_ALO + r * ASTR + c4);
        ph[0] = h0; ph[1] = h1;
        pl[0] = l0; pl[1] = l1;
    }
}

// ---------------------------------------------------------------------------
// Batched GCN-linear GEMM: C[g] = act(A[g] @ W + bias); g = blockIdx.x / tpg
// ---------------------------------------------------------------------------
template<int IN_TRANSFORM>
__global__ __launch_bounds__(256, 1)
void k_gemm_mma(const float* __restrict__ A0,
                const unsigned* __restrict__ whi, const unsigned* __restrict__ wlo,
                const float* __restrict__ bias, float* __restrict__ C0,
                const float* __restrict__ dis0, int M, int tpg)
{
    extern __shared__ __nv_bfloat16 smh[];
    const uint32_t sb = smem_u32(smh);
    const int tid = threadIdx.x;
    const int wid = tid >> 5, lid = tid & 31;
    const int g = blockIdx.x / tpg;
    const int bm = (blockIdx.x % tpg) * 128;
    const float* A  = A0 + (size_t)g * MAXN * HDIM;
    float* C        = C0 + (size_t)g * MAXN * HDIM;
    const float* dis = dis0 + (size_t)g * MAXN;

    for (int i = tid; i < 8192; i += 256) {
        int k = i >> 6, np = i & 63;
        *(unsigned*)(smh + SM_BHI + k * ASTR + np * 2) = __ldg(whi + i);
        *(unsigned*)(smh + SM_BLO + k * ASTR + np * 2) = __ldg(wlo + i);
    }
    load_a_tile<IN_TRANSFORM>(smh, A, dis, bm, M, tid);
    __syncthreads();

    const int wr = wid * 16;
    const int sub = lid >> 3, l7 = lid & 7;
    const uint32_t aHi = sb + (uint32_t)(SM_AHI + (wr + (sub & 1) * 8 + l7) * ASTR + (sub >> 1) * 8) * 2u;
    const uint32_t aLo = aHi + (uint32_t)(TH * 2);
    const uint32_t bHi = sb + (uint32_t)(SM_BHI + ((sub & 1) * 8 + l7) * ASTR + (sub >> 1) * 8) * 2u;
    const uint32_t bLo = bHi + (uint32_t)(TH * 2);

    float acc[16][4];
#pragma unroll
    for (int i = 0; i < 16; i++)
#pragma unroll
        for (int j = 0; j < 4; j++) acc[i][j] = 0.0f;

    gemm_mainloop(aHi, aLo, bHi, bLo, acc);

    const int gid = lid >> 2, tig = lid & 3;
    const int row0 = bm + wr + gid;
    const int row1 = row0 + 8;
#pragma unroll
    for (int nb = 0; nb < 16; nb++) {
        int col = nb * 8 + tig * 2;
        float2 bv = *(const float2*)(bias + col);
        if (row0 < M) {
            float2 o = make_float2(acc[nb][0] + bv.x, acc[nb][1] + bv.y);
            *(float2*)(C + (size_t)row0 * 128 + col) = o;
        }
        if (row1 < M) {
            float2 o = make_float2(acc[nb][2] + bv.x, acc[nb][3] + bv.y);
            *(float2*)(C + (size_t)row1 * 128 + col) = o;
        }
    }
}

// ---------------------------------------------------------------------------
// Fused encoder: h2 = relu(X @ W1 + b1) @ W2 + b2, both graphs batched.
// Each warp's A rows are private to it, so the intermediate is written back
// into the A smem tile with only a __syncwarp().
// ---------------------------------------------------------------------------
__global__ __launch_bounds__(256, 1)
void k_enc_fused(const float* __restrict__ x1, const float* __restrict__ x2,
                 const unsigned* __restrict__ wbf,
                 const float* __restrict__ b1, const float* __restrict__ b2,
                 float* __restrict__ C0, int M, int tpg)
{
    extern __shared__ __nv_bfloat16 smh[];
    const uint32_t sb = smem_u32(smh);
    const int tid = threadIdx.x;
    const int wid = tid >> 5, lid = tid & 31;
    const int g = blockIdx.x / tpg;
    const int bm = (blockIdx.x % tpg) * 128;
    const float* X = g ? x2 : x1;
    float* C = C0 + (size_t)g * MAXN * HDIM;

    for (int i = tid; i < 8192; i += 256) {
        int k = i >> 6, np = i & 63;
        int o = k * ASTR + np * 2;
        *(unsigned*)(smh + SM_BHI  + o) = __ldg(wbf + i);
        *(unsigned*)(smh + SM_BLO  + o) = __ldg(wbf + 8192 + i);
        *(unsigned*)(smh + SM_B2HI + o) = __ldg(wbf + 16384 + i);
        *(unsigned*)(smh + SM_B2LO + o) = __ldg(wbf + 24576 + i);
    }
    load_a_tile<0>(smh, X, (const float*)0, bm, M, tid);
    __syncthreads();

    const int wr = wid * 16;
    const int sub = lid >> 3, l7 = lid & 7;
    const uint32_t aHi = sb + (uint32_t)(SM_AHI + (wr + (sub & 1) * 8 + l7) * ASTR + (sub >> 1) * 8) * 2u;
    const uint32_t aLo = aHi + (uint32_t)(TH * 2);
    const uint32_t bOff = (uint32_t)(((sub & 1) * 8 + l7) * ASTR + (sub >> 1) * 8) * 2u;
    const uint32_t b1Hi = sb + (uint32_t)(SM_BHI)  * 2u + bOff;
    const uint32_t b1Lo = sb + (uint32_t)(SM_BLO)  * 2u + bOff;
    const uint32_t b2Hi = sb + (uint32_t)(SM_B2HI) * 2u + bOff;
    const uint32_t b2Lo = sb + (uint32_t)(SM_B2LO) * 2u + bOff;

    float acc[16][4];
#pragma unroll
    for (int i = 0; i < 16; i++)
#pragma unroll
        for (int j = 0; j < 4; j++) acc[i][j] = 0.0f;

    gemm_mainloop(aHi, aLo, b1Hi, b1Lo, acc);

    // mid-epilogue: relu(acc + b1) -> split -> back into this warp's A rows
    const int gid = lid >> 2, tig = lid & 3;
    const int r0 = wr + gid;
    const int r1 = r0 + 8;
#pragma unroll
    for (int nb = 0; nb < 16; nb++) {
        int col = nb * 8 + tig * 2;
        float2 bv = *(const float2*)(b1 + col);
        float v0 = fmaxf(acc[nb][0] + bv.x, 0.f);
        float v1 = fmaxf(acc[nb][1] + bv.y, 0.f);
        float v2 = fmaxf(acc[nb][2] + bv.x, 0.f);
        float v3 = fmaxf(acc[nb][3] + bv.y, 0.f);
        unsigned h, l;
        split2(v0, v1, h, l);
        *(unsigned*)(smh + SM_AHI + r0 * ASTR + col) = h;
        *(unsigned*)(smh + SM_ALO + r0 * ASTR + col) = l;
        split2(v2, v3, h, l);
        *(unsigned*)(smh + SM_AHI + r1 * ASTR + col) = h;
        *(unsigned*)(smh + SM_ALO + r1 * ASTR + col) = l;
        acc[nb][0] = 0.f; acc[nb][1] = 0.f; acc[nb][2] = 0.f; acc[nb][3] = 0.f;
    }
    __syncwarp();

    gemm_mainloop(aHi, aLo, b2Hi, b2Lo, acc);

    const int row0 = bm + r0;
    const int row1 = bm + r1;
#pragma unroll
    for (int nb = 0; nb < 16; nb++) {
        int col = nb * 8 + tig * 2;
        float2 bv = *(const float2*)(b2 + col);
        if (row0 < M) {
            float2 o = make_float2(acc[nb][0] + bv.x, acc[nb][1] + bv.y);
            *(float2*)(C + (size_t)row0 * 128 + col) = o;
        }
        if (row1 < M) {
            float2 o = make_float2(acc[nb][2] + bv.x, acc[nb][3] + bv.y);
            *(float2*)(C + (size_t)row1 * 128 + col) = o;
        }
    }
}

// ---------------------------------------------------------------------------
// CSR build (both graphs per launch via grid.y)
// ---------------------------------------------------------------------------
__global__ void k_deg2(const int* __restrict__ ei1, const int* __restrict__ ei2,
                       int E, int* __restrict__ icsr0)
{
    int e = blockIdx.x * blockDim.x + threadIdx.x;
    if (e >= E) return;
    const int* ei = blockIdx.y ? ei2 : ei1;
    int* deg = icsr0 + (size_t)blockIdx.y * ICSR;
    atomicAdd(&deg[ei[e]], 1);
}

__global__ void k_dis_offs2(int* __restrict__ icsr0, float* __restrict__ dis0,
                            int* __restrict__ offs0, int n)
{
    int i = blockIdx.x * blockDim.x + threadIdx.x;
    if (i >= n) return;
    int* deg  = icsr0 + (size_t)blockIdx.y * ICSR;
    int* gctr = deg + 2 * MAXN;
    float* dis = dis0 + (size_t)blockIdx.y * MAXN;
    int*   offs = offs0 + (size_t)blockIdx.y * MAXN;
    int d = deg[i];
    dis[i] = (d > 0) ? rsqrtf((float)d) : 0.0f;
    offs[i] = atomicAdd(gctr, d);
}

__global__ void k_scatter2(const int* __restrict__ ei1, const int* __restrict__ ei2,
                           int E, const int* __restrict__ offs0,
                           int* __restrict__ icsr0, int* __restrict__ cols0)
{
    int e = blockIdx.x * blockDim.x + threadIdx.x;
    if (e >= E) return;
    const int* ei = blockIdx.y ? ei2 : ei1;
    const int* offs = offs0 + (size_t)blockIdx.y * MAXN;
    int* cursor = icsr0 + (size_t)blockIdx.y * ICSR + MAXN;
    int* cols   = cols0 + (size_t)blockIdx.y * MAXE;
    int r = ei[e];
    int c = ei[E + e];
    int pos = offs[r] + atomicAdd(&cursor[r], 1);
    cols[pos] = c;
}

// ---------------------------------------------------------------------------
// CSR aggregation (batched): agg[n,:] = sum dis[c]*h[c,:]
// ---------------------------------------------------------------------------
__global__ void k_aggregate(const float* __restrict__ h0,
                            const int* __restrict__ offs0, const int* __restrict__ icsr0,
                            const int* __restrict__ cols0,
                            const float* __restrict__ dis0,
                            float* __restrict__ agg0, int n, int bpg)
{
    const int g = blockIdx.x / bpg;
    const int lb = blockIdx.x % bpg;
    int warp = lb * (blockDim.x >> 5) + (threadIdx.x >> 5);
    int lane = threadIdx.x & 31;
    if (warp >= n) return;
    const float* h   = h0   + (size_t)g * MAXN * HDIM;
    float* agg       = agg0 + (size_t)g * MAXN * HDIM;
    const int* offs  = offs0 + (size_t)g * MAXN;
    const int* deg   = icsr0 + (size_t)g * ICSR;
    const int* cols  = cols0 + (size_t)g * MAXE;
    const float* dis = dis0  + (size_t)g * MAXN;

    int s = __ldg(offs + warp);
    int e = s + __ldg(deg + warp);
    float4 a0 = make_float4(0.f, 0.f, 0.f, 0.f);
    float4 a1 = make_float4(0.f, 0.f, 0.f, 0.f);
    int i = s;
    for (; i + 2 <= e; i += 2) {
        int c0 = __ldg(cols + i), c1 = __ldg(cols + i + 1);
        float n0 = __ldg(dis + c0), n1 = __ldg(dis + c1);
        float4 v0 = *(const float4*)(h + (size_t)c0 * 128 + lane * 4);
        float4 v1 = *(const float4*)(h + (size_t)c1 * 128 + lane * 4);
        a0.x = fmaf(n0, v0.x, a0.x); a0.y = fmaf(n0, v0.y, a0.y);
        a0.z = fmaf(n0, v0.z, a0.z); a0.w = fmaf(n0, v0.w, a0.w);
        a1.x = fmaf(n1, v1.x, a1.x); a1.y = fmaf(n1, v1.y, a1.y);
        a1.z = fmaf(n1, v1.z, a1.z); a1.w = fmaf(n1, v1.w, a1.w);
    }
    if (i < e) {
        int c0 = __ldg(cols + i);
        float n0 = __ldg(dis + c0);
        float4 v0 = *(const float4*)(h + (size_t)c0 * 128 + lane * 4);
        a0.x = fmaf(n0, v0.x, a0.x); a0.y = fmaf(n0, v0.y, a0.y);
        a0.z = fmaf(n0, v0.z, a0.z); a0.w = fmaf(n0, v0.w, a0.w);
    }
    a0.x += a1.x; a0.y += a1.y; a0.z += a1.z; a0.w += a1.w;
    *(float4*)(agg + (size_t)warp * 128 + lane * 4) = a0;
}

// ---------------------------------------------------------------------------
// Fused aggregate + mean-pool (layer 2, batched)
// ---------------------------------------------------------------------------
__global__ void k_aggpool(const float* __restrict__ h0,
                          const int* __restrict__ offs0, const int* __restrict__ icsr0,
                          const int* __restrict__ cols0,
                          const float* __restrict__ dis0,
                          float* __restrict__ gsum0, int n, int bpg)
{
    __shared__ float gpart[128];
    if (threadIdx.x < 128) gpart[threadIdx.x] = 0.0f;
    __syncthreads();

    const int g = blockIdx.x / bpg;
    const int lb = blockIdx.x % bpg;
    int warp = lb * (blockDim.x >> 5) + (threadIdx.x >> 5);
    int lane = threadIdx.x & 31;
    const float* h   = h0   + (size_t)g * MAXN * HDIM;
    const int* offs  = offs0 + (size_t)g * MAXN;
    const int* deg   = icsr0 + (size_t)g * ICSR;
    const int* cols  = cols0 + (size_t)g * MAXE;
    const float* dis = dis0  + (size_t)g * MAXN;
    float* gsum      = gsum0 + (size_t)g * HDIM;

    if (warp < n) {
        int s = __ldg(offs + warp);
        int e = s + __ldg(deg + warp);
        float4 a0 = make_float4(0.f, 0.f, 0.f, 0.f);
        float4 a1 = make_float4(0.f, 0.f, 0.f, 0.f);
        int i = s;
        for (; i + 2 <= e; i += 2) {
            int c0 = __ldg(cols + i), c1 = __ldg(cols + i + 1);
            float n0 = __ldg(dis + c0), n1 = __ldg(dis + c1);
            float4 v0 = *(const float4*)(h + (size_t)c0 * 128 + lane * 4);
            float4 v1 = *(const float4*)(h + (size_t)c1 * 128 + lane * 4);
            a0.x = fmaf(n0, v0.x, a0.x); a0.y = fmaf(n0, v0.y, a0.y);
            a0.z = fmaf(n0, v0.z, a0.z); a0.w = fmaf(n0, v0.w, a0.w);
            a1.x = fmaf(n1, v1.x, a1.x); a1.y = fmaf(n1, v1.y, a1.y);
            a1.z = fmaf(n1, v1.z, a1.z); a1.w = fmaf(n1, v1.w, a1.w);
        }
        if (i < e) {
            int c0 = __ldg(cols + i);
            float n0 = __ldg(dis + c0);
            float4 v0 = *(const float4*)(h + (size_t)c0 * 128 + lane * 4);
            a0.x = fmaf(n0, v0.x, a0.x); a0.y = fmaf(n0, v0.y, a0.y);
            a0.z = fmaf(n0, v0.z, a0.z); a0.w = fmaf(n0, v0.w, a0.w);
        }
        float d = __ldg(dis + warp);
        atomicAdd(&gpart[lane * 4 + 0], fmaxf(d * (a0.x + a1.x), 0.f));
        atomicAdd(&gpart[lane * 4 + 1], fmaxf(d * (a0.y + a1.y), 0.f));
        atomicAdd(&gpart[lane * 4 + 2], fmaxf(d * (a0.z + a1.z), 0.f));
        atomicAdd(&gpart[lane * 4 + 3], fmaxf(d * (a0.w + a1.w), 0.f));
    }
    __syncthreads();
    if (threadIdx.x < 128) {
        float v = gpart[threadIdx.x];
        if (v != 0.0f) atomicAdd(&gsum[threadIdx.x], v);
    }
}

// ---------------------------------------------------------------------------
// final MLP
// ---------------------------------------------------------------------------
__global__ void k_final(const float* __restrict__ gsum,
                        const float* __restrict__ w1, const float* __restrict__ b1,
                        const float* __restrict__ w2, const float* __restrict__ b2,
                        float* __restrict__ out, float invN)
{
    __shared__ float cv[512];
    __shared__ float red[128];
    int t = threadIdx.x;
    float a = gsum[t] * invN;
    float b = gsum[128 + t] * invN;
    cv[t]       = a;
    cv[128 + t] = b;
    cv[256 + t] = fabsf(a - b);
    cv[384 + t] = a * b;
    __syncthreads();
    float acc = b1[t];
    for (int k = 0; k < 512; k++)
        acc = fmaf(cv[k], w1[k * 128 + t], acc);
    acc = fmaxf(acc, 0.f);
    red[t] = acc * w2[t];
    __syncthreads();
    for (int s = 64; s > 0; s >>= 1) {
        if (t < s) red[t] += red[t + s];
        __syncthreads();
    }
    if (t == 0) out[0] = red[0] + b2[0];
}

// ---------------------------------------------------------------------------
// launch — single stream, both graphs batched per kernel
// ---------------------------------------------------------------------------
extern "C" void kernel_launch(void* const* d_in, const int* in_sizes, int n_in,
                              void* d_out, int out_size)
{
    const float* x1  = (const float*)d_in[0];
    const int*   ei1 = (const int*)d_in[1];
    const float* x2  = (const float*)d_in[2];
    const int*   ei2 = (const int*)d_in[3];
    const float* enc_w1 = (const float*)d_in[4];
    const float* enc_b1 = (const float*)d_in[5];
    const float* enc_w2 = (const float*)d_in[6];
    const float* enc_b2 = (const float*)d_in[7];
    const float* conv1_w = (const float*)d_in[8];
    const float* conv1_b = (const float*)d_in[9];
    const float* conv2_w = (const float*)d_in[10];
    const float* conv2_b = (const float*)d_in[11];
    const float* sim_w1 = (const float*)d_in[12];
    const float* sim_b1 = (const float*)d_in[13];
    const float* sim_w2 = (const float*)d_in[14];
    const float* sim_b2 = (const float*)d_in[15];

    const int n = in_sizes[0] / HDIM;
    const int E = in_sizes[1] / 2;

    float *bufA, *bufB, *dis, *gsum;
    int *icsr, *offs, *cols;
    unsigned* wbf;
    cudaGetSymbolAddress((void**)&bufA, g_bufA);
    cudaGetSymbolAddress((void**)&bufB, g_bufB);
    cudaGetSymbolAddress((void**)&icsr, g_icsr);
    cudaGetSymbolAddress((void**)&dis,  g_dis);
    cudaGetSymbolAddress((void**)&offs, g_offs);
    cudaGetSymbolAddress((void**)&cols, g_csr_col);
    cudaGetSymbolAddress((void**)&gsum, g_gsum);
    cudaGetSymbolAddress((void**)&wbf,  g_wbf);

    cudaFuncSetAttribute(k_enc_fused,    cudaFuncAttributeMaxDynamicSharedMemorySize, SM6_BYTES);
    cudaFuncSetAttribute(k_gemm_mma<0>,  cudaFuncAttributeMaxDynamicSharedMemorySize, SM_BYTES);
    cudaFuncSetAttribute(k_gemm_mma<1>,  cudaFuncAttributeMaxDynamicSharedMemorySize, SM_BYTES);

    const int tpg      = (n + 127) / 128;          // GEMM tiles per graph
    const int eBlocks  = (E + 255) / 256;
    const int nBlocks  = (n + 255) / 256;
    const int bpg      = (n * 32 + 255) / 256;     // aggregate blocks per graph

    // --- prep ---
    cudaMemsetAsync(gsum, 0, 2 * HDIM * sizeof(float));
    cudaMemsetAsync(icsr, 0, 2 * ICSR * sizeof(int));
    {
        dim3 grid(32, 4);
        k_convw<<<grid, 256>>>(enc_w1, enc_w2, conv1_w, conv2_w, wbf);
    }

    // --- CSR build (both graphs) ---
    {
        dim3 gE(eBlocks, 2), gN(nBlocks, 2);
        k_deg2<<<gE, 256>>>(ei1, ei2, E, icsr);
        k_dis_offs2<<<gN, 256>>>(icsr, dis, offs, n);
        k_scatter2<<<gE, 256>>>(ei1, ei2, E, offs, icsr, cols);
    }

    // --- fused encoder MLP (both graphs) -> bufB ---
    k_enc_fused<<<2 * tpg, 256, SM6_BYTES>>>(x1, x2, wbf, enc_b1, enc_b2, bufB, n, tpg);

    // --- GCN layer 1 ---
    k_gemm_mma<0><<<2 * tpg, 256, SM_BYTES>>>(bufB, wbf + 4 * 8192, wbf + 5 * 8192,
                                              conv1_b, bufA, dis, n, tpg);
    k_aggregate<<<2 * bpg, 256>>>(bufA, offs, icsr, cols, dis, bufB, n, bpg);

    // --- GCN layer 2 (relu(dis*agg) fused into GEMM; pool fused into agg) ---
    k_gemm_mma<1><<<2 * tpg, 256, SM_BYTES>>>(bufB, wbf + 6 * 8192, wbf + 7 * 8192,
                                              conv2_b, bufA, dis, n, tpg);
    k_aggpool<<<2 * bpg, 256>>>(bufA, offs, icsr, cols, dis, gsum, n, bpg);

    // --- final MLP ---
    k_final<<<1, 128>>>(gsum, sim_w1, sim_b1, sim_w2, sim_b2,
                        (float*)d_out, 1.0f / (float)n);
}

// round 9
// speedup vs baseline: 1.8558x; 1.0714x over previous
#include <cuda_runtime.h>
#include <cuda_bf16.h>
#include <math.h>
#include <stdint.h>

// ---------------------------------------------------------------------------
// GraphSimilarity: 2x { [enc1+enc2+conv1 fused 3-GEMM] -> agg -> conv2-GEMM
//                       -> agg+pool } -> similarity MLP -> scalar
// GEMMs on mma.sync (bf16 3-term split, fp32 acc). CSR built without a scan.
// Both graphs batched into every kernel launch (single stream).
// ---------------------------------------------------------------------------

#define MAXN 50000
#define MAXE 800000
#define HDIM 128
#define ICSR (2 * MAXN + 1)

__device__ __align__(16) float g_bufA[2][MAXN * HDIM];
__device__ __align__(16) float g_bufB[2][MAXN * HDIM];
__device__ int   g_icsr[2][ICSR];     // deg | cursor | gctr
__device__ float g_dis[2][MAXN];
__device__ int   g_offs[2][MAXN];
__device__ int   g_csr_col[2][MAXE];
__device__ float g_gsum[2 * HDIM];
// bf16 weight splits: 8 images (w1hi,w1lo,w2hi,w2lo,c1hi,c1lo,c2hi,c2lo) x 8192 u32
__device__ __align__(16) unsigned g_wbf[8][8192];

// ======================= helpers ===========================================
__device__ __forceinline__ uint32_t smem_u32(const void* p) {
    uint32_t a;
    asm("{ .reg .u64 t; cvta.to.shared.u64 t, %1; cvt.u32.u64 %0, t; }" : "=r"(a) : "l"(p));
    return a;
}
__device__ __forceinline__ void ldsm_x4(uint32_t addr, uint32_t r[4]) {
    asm volatile("ldmatrix.sync.aligned.m8n8.x4.shared.b16 {%0,%1,%2,%3}, [%4];"
                 : "=r"(r[0]), "=r"(r[1]), "=r"(r[2]), "=r"(r[3]) : "r"(addr));
}
__device__ __forceinline__ void ldsm_x4t(uint32_t addr, uint32_t r[4]) {
    asm volatile("ldmatrix.sync.aligned.m8n8.x4.trans.shared.b16 {%0,%1,%2,%3}, [%4];"
                 : "=r"(r[0]), "=r"(r[1]), "=r"(r[2]), "=r"(r[3]) : "r"(addr));
}
__device__ __forceinline__ void mma16816(float c[4], const uint32_t a[4],
                                         uint32_t b0, uint32_t b1) {
    asm volatile(
        "mma.sync.aligned.m16n8k16.row.col.f32.bf16.bf16.f32 "
        "{%0,%1,%2,%3}, {%4,%5,%6,%7}, {%8,%9}, {%0,%1,%2,%3};"
        : "+f"(c[0]), "+f"(c[1]), "+f"(c[2]), "+f"(c[3])
        : "r"(a[0]), "r"(a[1]), "r"(a[2]), "r"(a[3]), "r"(b0), "r"(b1));
}
// packed rn split: hi/lo bf16 pairs for 2 fp32 values (low half = v0)
__device__ __forceinline__ void split2(float v0, float v1, unsigned& hi, unsigned& lo) {
    unsigned h;
    asm("cvt.rn.bf16x2.f32 %0, %1, %2;" : "=r"(h) : "f"(v1), "f"(v0));
    float f0 = __uint_as_float(h << 16);
    float f1 = __uint_as_float(h & 0xFFFF0000u);
    float r0 = v0 - f0, r1 = v1 - f1;
    unsigned l;
    asm("cvt.rn.bf16x2.f32 %0, %1, %2;" : "=r"(l) : "f"(r1), "f"(r0));
    hi = h; lo = l;
}

// ---------------------------------------------------------------------------
// Weight prep: 4 weights, one launch (grid.y selects weight).
// ---------------------------------------------------------------------------
__global__ void k_convw(const float* __restrict__ w0, const float* __restrict__ w1,
                        const float* __restrict__ w2, const float* __restrict__ w3,
                        unsigned* __restrict__ wbf)
{
    int idx = blockIdx.x * blockDim.x + threadIdx.x;   // 8192 = 128k * 64 n-pairs
    if (idx >= 8192) return;
    const float* W = (blockIdx.y == 0) ? w0 : (blockIdx.y == 1) ? w1
                   : (blockIdx.y == 2) ? w2 : w3;
    unsigned* hi = wbf + (size_t)(2 * blockIdx.y) * 8192;
    unsigned* lo = hi + 8192;
    int k = idx >> 6;
    int n = (idx & 63) * 2;
    unsigned h, l;
    split2(W[(size_t)k * 128 + n], W[(size_t)k * 128 + n + 1], h, l);
    hi[idx] = h;
    lo[idx] = l;
}

// ---------------------------------------------------------------------------
// GEMM tiling constants
// ---------------------------------------------------------------------------
#define ASTR 136
#define TH   (128 * ASTR)          // halves per 128-row image
#define TH64 (64 * ASTR)           // halves per 64-row image

// enc3 smem layout (halves): A hi/lo + W slot1 hi/lo + W slot2 hi/lo
#define E_AHI 0
#define E_ALO TH
#define E_B1HI (2 * TH)
#define E_B1LO (3 * TH)
#define E_B2HI (4 * TH)
#define E_B2LO (5 * TH)
#define SM_ENC3 (6 * TH * 2)       // 208896 B

// gemm64 smem layout (halves)
#define G_AHI 0
#define G_ALO TH64
#define G_BHI (2 * TH64)
#define G_BLO (2 * TH64 + TH)
#define SM_G64 ((2 * TH64 + 2 * TH) * 2)   // 104448 B

__device__ __forceinline__ void gemm_mainloop(uint32_t aHi, uint32_t aLo,
                                              uint32_t bHi, uint32_t bLo,
                                              float acc[16][4])
{
#pragma unroll
    for (int ks = 0; ks < 8; ks++) {
        const uint32_t kb = (uint32_t)(ks * 16) * 2u;
        uint32_t ah[4], al[4];
        ldsm_x4(aHi + kb, ah);
        ldsm_x4(aLo + kb, al);
        const uint32_t kRowB = (uint32_t)(ks * 16 * ASTR) * 2u;
#pragma unroll
        for (int nb = 0; nb < 8; nb++) {
            uint32_t bh[4], bl[4];
            const uint32_t nOff = (uint32_t)(nb * 16) * 2u;
            ldsm_x4t(bHi + kRowB + nOff, bh);
            ldsm_x4t(bLo + kRowB + nOff, bl);
            mma16816(acc[nb * 2],     ah, bh[0], bh[1]);
            mma16816(acc[nb * 2 + 1], ah, bh[2], bh[3]);
            mma16816(acc[nb * 2],     ah, bl[0], bl[1]);
            mma16816(acc[nb * 2 + 1], ah, bl[2], bl[3]);
            mma16816(acc[nb * 2],     al, bh[0], bh[1]);
            mma16816(acc[nb * 2 + 1], al, bh[2], bh[3]);
        }
    }
}

// ---------------------------------------------------------------------------
// Fused encoder + conv1: h3 = (relu(X W1 + b1) W2 + b2) W3 + b3
// Both graphs batched. Intermediates live in each warp's private A smem rows.
// W3 is reloaded into the W1 slot mid-kernel (doesn't fit otherwise).
// ---------------------------------------------------------------------------
__global__ __launch_bounds__(256, 1)
void k_enc3(const float* __restrict__ x1, const float* __restrict__ x2,
            const unsigned* __restrict__ wbf,
            const float* __restrict__ b1, const float* __restrict__ b2,
            const float* __restrict__ b3,
            float* __restrict__ C0, int M, int tpg)
{
    extern __shared__ __nv_bfloat16 smh[];
    const uint32_t sb = smem_u32(smh);
    const int tid = threadIdx.x;
    const int wid = tid >> 5, lid = tid & 31;
    const int g = blockIdx.x / tpg;
    const int bm = (blockIdx.x % tpg) * 128;
    const float* X = g ? x2 : x1;
    float* C = C0 + (size_t)g * MAXN * HDIM;

    // W1 -> slot1, W2 -> slot2
    for (int i = tid; i < 8192; i += 256) {
        int k = i >> 6, np = i & 63;
        int o = k * ASTR + np * 2;
        *(unsigned*)(smh + E_B1HI + o) = __ldg(wbf + i);
        *(unsigned*)(smh + E_B1LO + o) = __ldg(wbf + 8192 + i);
        *(unsigned*)(smh + E_B2HI + o) = __ldg(wbf + 16384 + i);
        *(unsigned*)(smh + E_B2LO + o) = __ldg(wbf + 24576 + i);
    }
    // A tile (128x128 fp32 -> hi/lo)
    for (int i = tid; i < 4096; i += 256) {
        int r = i >> 5, c4 = (i & 31) * 4;
        int grow = bm + r;
        float4 v = make_float4(0.f, 0.f, 0.f, 0.f);
        if (grow < M) v = *(const float4*)(X + (size_t)grow * 128 + c4);
        unsigned h0, l0, h1, l1;
        split2(v.x, v.y, h0, l0);
        split2(v.z, v.w, h1, l1);
        unsigned* ph = (unsigned*)(smh + E_AHI + r * ASTR + c4);
        unsigned* pl = (unsigned*)(smh + E_ALO + r * ASTR + c4);
        ph[0] = h0; ph[1] = h1;
        pl[0] = l0; pl[1] = l1;
    }
    __syncthreads();

    const int wr = wid * 16;
    const int sub = lid >> 3, l7 = lid & 7;
    const uint32_t aHi = sb + (uint32_t)(E_AHI + (wr + (sub & 1) * 8 + l7) * ASTR + (sub >> 1) * 8) * 2u;
    const uint32_t aLo = aHi + (uint32_t)(TH * 2);
    const uint32_t bOff = (uint32_t)(((sub & 1) * 8 + l7) * ASTR + (sub >> 1) * 8) * 2u;
    const uint32_t b1Hi = sb + (uint32_t)(E_B1HI) * 2u + bOff;
    const uint32_t b1Lo = sb + (uint32_t)(E_B1LO) * 2u + bOff;
    const uint32_t b2Hi = sb + (uint32_t)(E_B2HI) * 2u + bOff;
    const uint32_t b2Lo = sb + (uint32_t)(E_B2LO) * 2u + bOff;

    const int gid = lid >> 2, tig = lid & 3;
    const int r0 = wr + gid;
    const int r1 = r0 + 8;

    float acc[16][4];
#pragma unroll
    for (int i = 0; i < 16; i++)
#pragma unroll
        for (int j = 0; j < 4; j++) acc[i][j] = 0.0f;

    // ---- GEMM 1: relu(X W1 + b1) -> A ----
    gemm_mainloop(aHi, aLo, b1Hi, b1Lo, acc);
#pragma unroll
    for (int nb = 0; nb < 16; nb++) {
        int col = nb * 8 + tig * 2;
        float2 bv = *(const float2*)(b1 + col);
        float v0 = fmaxf(acc[nb][0] + bv.x, 0.f);
        float v1 = fmaxf(acc[nb][1] + bv.y, 0.f);
        float v2 = fmaxf(acc[nb][2] + bv.x, 0.f);
        float v3 = fmaxf(acc[nb][3] + bv.y, 0.f);
        unsigned h, l;
        split2(v0, v1, h, l);
        *(unsigned*)(smh + E_AHI + r0 * ASTR + col) = h;
        *(unsigned*)(smh + E_ALO + r0 * ASTR + col) = l;
        split2(v2, v3, h, l);
        *(unsigned*)(smh + E_AHI + r1 * ASTR + col) = h;
        *(unsigned*)(smh + E_ALO + r1 * ASTR + col) = l;
        acc[nb][0] = 0.f; acc[nb][1] = 0.f; acc[nb][2] = 0.f; acc[nb][3] = 0.f;
    }
    __syncwarp();

    // ---- GEMM 2: (.) W2 + b2 -> A  (no relu) ----
    gemm_mainloop(aHi, aLo, b2Hi, b2Lo, acc);
#pragma unroll
    for (int nb = 0; nb < 16; nb++) {
        int col = nb * 8 + tig * 2;
        float2 bv = *(const float2*)(b2 + col);
        float v0 = acc[nb][0] + bv.x;
        float v1 = acc[nb][1] + bv.y;
        float v2 = acc[nb][2] + bv.x;
        float v3 = acc[nb][3] + bv.y;
        unsigned h, l;
        split2(v0, v1, h, l);
        *(unsigned*)(smh + E_AHI + r0 * ASTR + col) = h;
        *(unsigned*)(smh + E_ALO + r0 * ASTR + col) = l;
        split2(v2, v3, h, l);
        *(unsigned*)(smh + E_AHI + r1 * ASTR + col) = h;
        *(unsigned*)(smh + E_ALO + r1 * ASTR + col) = l;
        acc[nb][0] = 0.f; acc[nb][1] = 0.f; acc[nb][2] = 0.f; acc[nb][3] = 0.f;
    }

    // ---- reload W3 (conv1) into slot1 ----
    __syncthreads();   // all warps done with W1/W2 reads + private A writes
    for (int i = tid; i < 8192; i += 256) {
        int k = i >> 6, np = i & 63;
        int o = k * ASTR + np * 2;
        *(unsigned*)(smh + E_B1HI + o) = __ldg(wbf + 32768 + i);
        *(unsigned*)(smh + E_B1LO + o) = __ldg(wbf + 40960 + i);
    }
    __syncthreads();

    // ---- GEMM 3: (.) W3 + b3 -> gmem ----
    gemm_mainloop(aHi, aLo, b1Hi, b1Lo, acc);
    const int row0 = bm + r0;
    const int row1 = bm + r1;
#pragma unroll
    for (int nb = 0; nb < 16; nb++) {
        int col = nb * 8 + tig * 2;
        float2 bv = *(const float2*)(b3 + col);
        if (row0 < M) {
            float2 o = make_float2(acc[nb][0] + bv.x, acc[nb][1] + bv.y);
            *(float2*)(C + (size_t)row0 * 128 + col) = o;
        }
        if (row1 < M) {
            float2 o = make_float2(acc[nb][2] + bv.x, acc[nb][3] + bv.y);
            *(float2*)(C + (size_t)row1 * 128 + col) = o;
        }
    }
}

// ---------------------------------------------------------------------------
// GCN-2 GEMM, BM=64 / 128 threads (2 CTAs/SM): C = relu(dis*A) @ W + bias
// ---------------------------------------------------------------------------
__global__ __launch_bounds__(128, 2)
void k_gemm64(const float* __restrict__ A0,
              const unsigned* __restrict__ whi, const unsigned* __restrict__ wlo,
              const float* __restrict__ bias, float* __restrict__ C0,
              const float* __restrict__ dis0, int M, int tpg)
{
    extern __shared__ __nv_bfloat16 smh[];
    const uint32_t sb = smem_u32(smh);
    const int tid = threadIdx.x;
    const int wid = tid >> 5, lid = tid & 31;
    const int g = blockIdx.x / tpg;
    const int bm = (blockIdx.x % tpg) * 64;
    const float* A   = A0 + (size_t)g * MAXN * HDIM;
    float* C         = C0 + (size_t)g * MAXN * HDIM;
    const float* dis = dis0 + (size_t)g * MAXN;

    for (int i = tid; i < 8192; i += 128) {
        int k = i >> 6, np = i & 63;
        int o = k * ASTR + np * 2;
        *(unsigned*)(smh + G_BHI + o) = __ldg(whi + i);
        *(unsigned*)(smh + G_BLO + o) = __ldg(wlo + i);
    }
    for (int i = tid; i < 2048; i += 128) {            // 64 rows x 32 float4
        int r = i >> 5, c4 = (i & 31) * 4;
        int grow = bm + r;
        float4 v = make_float4(0.f, 0.f, 0.f, 0.f);
        if (grow < M) {
            v = *(const float4*)(A + (size_t)grow * 128 + c4);
            float dv = dis[grow];
            v.x = fmaxf(v.x * dv, 0.f); v.y = fmaxf(v.y * dv, 0.f);
            v.z = fmaxf(v.z * dv, 0.f); v.w = fmaxf(v.w * dv, 0.f);
        }
        unsigned h0, l0, h1, l1;
        split2(v.x, v.y, h0, l0);
        split2(v.z, v.w, h1, l1);
        unsigned* ph = (unsigned*)(smh + G_AHI + r * ASTR + c4);
        unsigned* pl = (unsigned*)(smh + G_ALO + r * ASTR + c4);
        ph[0] = h0; ph[1] = h1;
        pl[0] = l0; pl[1] = l1;
    }
    __syncthreads();

    const int wr = wid * 16;                          // 4 warps x 16 rows = 64
    const int sub = lid >> 3, l7 = lid & 7;
    const uint32_t aHi = sb + (uint32_t)(G_AHI + (wr + (sub & 1) * 8 + l7) * ASTR + (sub >> 1) * 8) * 2u;
    const uint32_t aLo = aHi + (uint32_t)(TH64 * 2);
    const uint32_t bHi = sb + (uint32_t)(G_BHI + ((sub & 1) * 8 + l7) * ASTR + (sub >> 1) * 8) * 2u;
    const uint32_t bLo = bHi + (uint32_t)(TH * 2);

    float acc[16][4];
#pragma unroll
    for (int i = 0; i < 16; i++)
#pragma unroll
        for (int j = 0; j < 4; j++) acc[i][j] = 0.0f;

    gemm_mainloop(aHi, aLo, bHi, bLo, acc);

    const int gid = lid >> 2, tig = lid & 3;
    const int row0 = bm + wr + gid;
    const int row1 = row0 + 8;
#pragma unroll
    for (int nb = 0; nb < 16; nb++) {
        int col = nb * 8 + tig * 2;
        float2 bv = *(const float2*)(bias + col);
        if (row0 < M) {
            float2 o = make_float2(acc[nb][0] + bv.x, acc[nb][1] + bv.y);
            *(float2*)(C + (size_t)row0 * 128 + col) = o;
        }
        if (row1 < M) {
            float2 o = make_float2(acc[nb][2] + bv.x, acc[nb][3] + bv.y);
            *(float2*)(C + (size_t)row1 * 128 + col) = o;
        }
    }
}

// ---------------------------------------------------------------------------
// CSR build (both graphs per launch via grid.y)
// ---------------------------------------------------------------------------
__global__ void k_deg2(const int* __restrict__ ei1, const int* __restrict__ ei2,
                       int E, int* __restrict__ icsr0)
{
    int e = blockIdx.x * blockDim.x + threadIdx.x;
    if (e >= E) return;
    const int* ei = blockIdx.y ? ei2 : ei1;
    int* deg = icsr0 + (size_t)blockIdx.y * ICSR;
    atomicAdd(&deg[ei[e]], 1);
}

__global__ void k_dis_offs2(int* __restrict__ icsr0, float* __restrict__ dis0,
                            int* __restrict__ offs0, int n)
{
    int i = blockIdx.x * blockDim.x + threadIdx.x;
    if (i >= n) return;
    int* deg  = icsr0 + (size_t)blockIdx.y * ICSR;
    int* gctr = deg + 2 * MAXN;
    float* dis = dis0 + (size_t)blockIdx.y * MAXN;
    int*   offs = offs0 + (size_t)blockIdx.y * MAXN;
    int d = deg[i];
    dis[i] = (d > 0) ? rsqrtf((float)d) : 0.0f;
    offs[i] = atomicAdd(gctr, d);
}

__global__ void k_scatter2(const int* __restrict__ ei1, const int* __restrict__ ei2,
                           int E, const int* __restrict__ offs0,
                           int* __restrict__ icsr0, int* __restrict__ cols0)
{
    int e = blockIdx.x * blockDim.x + threadIdx.x;
    if (e >= E) return;
    const int* ei = blockIdx.y ? ei2 : ei1;
    const int* offs = offs0 + (size_t)blockIdx.y * MAXN;
    int* cursor = icsr0 + (size_t)blockIdx.y * ICSR + MAXN;
    int* cols   = cols0 + (size_t)blockIdx.y * MAXE;
    int r = ei[e];
    int c = ei[E + e];
    int pos = offs[r] + atomicAdd(&cursor[r], 1);
    cols[pos] = c;
}

// ---------------------------------------------------------------------------
// edge-gather inner step
// ---------------------------------------------------------------------------
__device__ __forceinline__ void agg_step(const float* __restrict__ h,
                                         const int* __restrict__ cols,
                                         const float* __restrict__ dis,
                                         int i, int lane, float4& a)
{
    int c = __ldg(cols + i);
    float nr = __ldg(dis + c);
    float4 v = *(const float4*)(h + (size_t)c * 128 + lane * 4);
    a.x = fmaf(nr, v.x, a.x); a.y = fmaf(nr, v.y, a.y);
    a.z = fmaf(nr, v.z, a.z); a.w = fmaf(nr, v.w, a.w);
}

// ---------------------------------------------------------------------------
// CSR aggregation (batched, 4-way unrolled): agg[n,:] = sum dis[c]*h[c,:]
// ---------------------------------------------------------------------------
__global__ void k_aggregate(const float* __restrict__ h0,
                            const int* __restrict__ offs0, const int* __restrict__ icsr0,
                            const int* __restrict__ cols0,
                            const float* __restrict__ dis0,
                            float* __restrict__ agg0, int n, int bpg)
{
    const int g = blockIdx.x / bpg;
    const int lb = blockIdx.x % bpg;
    int warp = lb * (blockDim.x >> 5) + (threadIdx.x >> 5);
    int lane = threadIdx.x & 31;
    if (warp >= n) return;
    const float* h   = h0    + (size_t)g * MAXN * HDIM;
    float* agg       = agg0  + (size_t)g * MAXN * HDIM;
    const int* offs  = offs0 + (size_t)g * MAXN;
    const int* deg   = icsr0 + (size_t)g * ICSR;
    const int* cols  = cols0 + (size_t)g * MAXE;
    const float* dis = dis0  + (size_t)g * MAXN;

    int s = __ldg(offs + warp);
    int e = s + __ldg(deg + warp);
    float4 a0 = make_float4(0.f, 0.f, 0.f, 0.f);
    float4 a1 = make_float4(0.f, 0.f, 0.f, 0.f);
    float4 a2 = make_float4(0.f, 0.f, 0.f, 0.f);
    float4 a3 = make_float4(0.f, 0.f, 0.f, 0.f);
    int i = s;
    for (; i + 4 <= e; i += 4) {
        agg_step(h, cols, dis, i + 0, lane, a0);
        agg_step(h, cols, dis, i + 1, lane, a1);
        agg_step(h, cols, dis, i + 2, lane, a2);
        agg_step(h, cols, dis, i + 3, lane, a3);
    }
    if (i + 2 <= e) {
        agg_step(h, cols, dis, i + 0, lane, a0);
        agg_step(h, cols, dis, i + 1, lane, a1);
        i += 2;
    }
    if (i < e) agg_step(h, cols, dis, i, lane, a0);
    a0.x += a1.x + a2.x + a3.x;
    a0.y += a1.y + a2.y + a3.y;
    a0.z += a1.z + a2.z + a3.z;
    a0.w += a1.w + a2.w + a3.w;
    *(float4*)(agg + (size_t)warp * 128 + lane * 4) = a0;
}

// ---------------------------------------------------------------------------
// Fused aggregate + mean-pool (layer 2, batched, 4-way unrolled)
// ---------------------------------------------------------------------------
__global__ void k_aggpool(const float* __restrict__ h0,
                          const int* __restrict__ offs0, const int* __restrict__ icsr0,
                          const int* __restrict__ cols0,
                          const float* __restrict__ dis0,
                          float* __restrict__ gsum0, int n, int bpg)
{
    __shared__ float gpart[128];
    if (threadIdx.x < 128) gpart[threadIdx.x] = 0.0f;
    __syncthreads();

    const int g = blockIdx.x / bpg;
    const int lb = blockIdx.x % bpg;
    int warp = lb * (blockDim.x >> 5) + (threadIdx.x >> 5);
    int lane = threadIdx.x & 31;
    const float* h   = h0    + (size_t)g * MAXN * HDIM;
    const int* offs  = offs0 + (size_t)g * MAXN;
    const int* deg   = icsr0 + (size_t)g * ICSR;
    const int* cols  = cols0 + (size_t)g * MAXE;
    const float* dis = dis0  + (size_t)g * MAXN;
    float* gsum      = gsum0 + (size_t)g * HDIM;

    if (warp < n) {
        int s = __ldg(offs + warp);
        int e = s + __ldg(deg + warp);
        float4 a0 = make_float4(0.f, 0.f, 0.f, 0.f);
        float4 a1 = make_float4(0.f, 0.f, 0.f, 0.f);
        float4 a2 = make_float4(0.f, 0.f, 0.f, 0.f);
        float4 a3 = make_float4(0.f, 0.f, 0.f, 0.f);
        int i = s;
        for (; i + 4 <= e; i += 4) {
            agg_step(h, cols, dis, i + 0, lane, a0);
            agg_step(h, cols, dis, i + 1, lane, a1);
            agg_step(h, cols, dis, i + 2, lane, a2);
            agg_step(h, cols, dis, i + 3, lane, a3);
        }
        if (i + 2 <= e) {
            agg_step(h, cols, dis, i + 0, lane, a0);
            agg_step(h, cols, dis, i + 1, lane, a1);
            i += 2;
        }
        if (i < e) agg_step(h, cols, dis, i, lane, a0);
        float d = __ldg(dis + warp);
        atomicAdd(&gpart[lane * 4 + 0], fmaxf(d * (a0.x + a1.x + a2.x + a3.x), 0.f));
        atomicAdd(&gpart[lane * 4 + 1], fmaxf(d * (a0.y + a1.y + a2.y + a3.y), 0.f));
        atomicAdd(&gpart[lane * 4 + 2], fmaxf(d * (a0.z + a1.z + a2.z + a3.z), 0.f));
        atomicAdd(&gpart[lane * 4 + 3], fmaxf(d * (a0.w + a1.w + a2.w + a3.w), 0.f));
    }
    __syncthreads();
    if (threadIdx.x < 128) {
        float v = gpart[threadIdx.x];
        if (v != 0.0f) atomicAdd(&gsum[threadIdx.x], v);
    }
}

// ---------------------------------------------------------------------------
// final MLP
// ---------------------------------------------------------------------------
__global__ void k_final(const float* __restrict__ gsum,
                        const float* __restrict__ w1, const float* __restrict__ b1,
                        const float* __restrict__ w2, const float* __restrict__ b2,
                        float* __restrict__ out, float invN)
{
    __shared__ float cv[512];
    __shared__ float red[128];
    int t = threadIdx.x;
    float a = gsum[t] * invN;
    float b = gsum[128 + t] * invN;
    cv[t]       = a;
    cv[128 + t] = b;
    cv[256 + t] = fabsf(a - b);
    cv[384 + t] = a * b;
    __syncthreads();
    float acc = b1[t];
    for (int k = 0; k < 512; k++)
        acc = fmaf(cv[k], w1[k * 128 + t], acc);
    acc = fmaxf(acc, 0.f);
    red[t] = acc * w2[t];
    __syncthreads();
    for (int s = 64; s > 0; s >>= 1) {
        if (t < s) red[t] += red[t + s];
        __syncthreads();
    }
    if (t == 0) out[0] = red[0] + b2[0];
}

// ---------------------------------------------------------------------------
// launch — single stream, both graphs batched per kernel
// ---------------------------------------------------------------------------
extern "C" void kernel_launch(void* const* d_in, const int* in_sizes, int n_in,
                              void* d_out, int out_size)
{
    const float* x1  = (const float*)d_in[0];
    const int*   ei1 = (const int*)d_in[1];
    const float* x2  = (const float*)d_in[2];
    const int*   ei2 = (const int*)d_in[3];
    const float* enc_w1 = (const float*)d_in[4];
    const float* enc_b1 = (const float*)d_in[5];
    const float* enc_w2 = (const float*)d_in[6];
    const float* enc_b2 = (const float*)d_in[7];
    const float* conv1_w = (const float*)d_in[8];
    const float* conv1_b = (const float*)d_in[9];
    const float* conv2_w = (const float*)d_in[10];
    const float* conv2_b = (const float*)d_in[11];
    const float* sim_w1 = (const float*)d_in[12];
    const float* sim_b1 = (const float*)d_in[13];
    const float* sim_w2 = (const float*)d_in[14];
    const float* sim_b2 = (const float*)d_in[15];

    const int n = in_sizes[0] / HDIM;
    const int E = in_sizes[1] / 2;

    float *bufA, *bufB, *dis, *gsum;
    int *icsr, *offs, *cols;
    unsigned* wbf;
    cudaGetSymbolAddress((void**)&bufA, g_bufA);
    cudaGetSymbolAddress((void**)&bufB, g_bufB);
    cudaGetSymbolAddress((void**)&icsr, g_icsr);
    cudaGetSymbolAddress((void**)&dis,  g_dis);
    cudaGetSymbolAddress((void**)&offs, g_offs);
    cudaGetSymbolAddress((void**)&cols, g_csr_col);
    cudaGetSymbolAddress((void**)&gsum, g_gsum);
    cudaGetSymbolAddress((void**)&wbf,  g_wbf);

    cudaFuncSetAttribute(k_enc3,   cudaFuncAttributeMaxDynamicSharedMemorySize, SM_ENC3);
    cudaFuncSetAttribute(k_gemm64, cudaFuncAttributeMaxDynamicSharedMemorySize, SM_G64);

    const int tpg128   = (n + 127) / 128;          // 128-row tiles per graph
    const int tpg64    = (n + 63) / 64;            // 64-row tiles per graph
    const int eBlocks  = (E + 255) / 256;
    const int nBlocks  = (n + 255) / 256;
    const int bpg      = (n * 32 + 255) / 256;     // aggregate blocks per graph

    // --- prep ---
    cudaMemsetAsync(gsum, 0, 2 * HDIM * sizeof(float));
    cudaMemsetAsync(icsr, 0, 2 * ICSR * sizeof(int));
    {
        dim3 grid(32, 4);
        k_convw<<<grid, 256>>>(enc_w1, enc_w2, conv1_w, conv2_w, wbf);
    }

    // --- CSR build (both graphs) ---
    {
        dim3 gE(eBlocks, 2), gN(nBlocks, 2);
        k_deg2<<<gE, 256>>>(ei1, ei2, E, icsr);
        k_dis_offs2<<<gN, 256>>>(icsr, dis, offs, n);
        k_scatter2<<<gE, 256>>>(ei1, ei2, E, offs, icsr, cols);
    }

    // --- fused encoder + conv1 (both graphs) -> bufA ---
    k_enc3<<<2 * tpg128, 256, SM_ENC3>>>(x1, x2, wbf, enc_b1, enc_b2, conv1_b,
                                         bufA, n, tpg128);

    // --- aggregate 1 -> bufB ---
    k_aggregate<<<2 * bpg, 256>>>(bufA, offs, icsr, cols, dis, bufB, n, bpg);

    // --- GCN layer 2 GEMM (relu(dis*agg) fused into prologue) -> bufA ---
    k_gemm64<<<2 * tpg64, 128, SM_G64>>>(bufB, wbf + 6 * 8192, wbf + 7 * 8192,
                                         conv2_b, bufA, dis, n, tpg64);

    // --- aggregate 2 + mean pool -> gsum ---
    k_aggpool<<<2 * bpg, 256>>>(bufA, offs, icsr, cols, dis, gsum, n, bpg);

    // --- final MLP ---
    k_final<<<1, 128>>>(gsum, sim_w1, sim_b1, sim_w2, sim_b2,
                        (float*)d_out, 1.0f / (float)n);
}

// round 10
// speedup vs baseline: 2.0046x; 1.0802x over previous
#include <cuda_runtime.h>
#include <cuda_bf16.h>
#include <math.h>
#include <stdint.h>

// ---------------------------------------------------------------------------
// GraphSimilarity: 2x { [enc1+enc2+conv1 fused 3-GEMM] -> agg -> conv2-GEMM
//                       -> agg+pool } -> similarity MLP -> scalar
// GEMMs on mma.sync (bf16 3-term split, fp32 acc). CSR built without a scan,
// scatter without cursor atomics (edge ranks captured during degree count).
// Aggregation inputs (h) stored as packed bf16x2 -> gather traffic halved.
// Both graphs batched into every kernel launch (single stream).
// ---------------------------------------------------------------------------

#define MAXN 50000
#define MAXE 800000
#define HDIM 128
#define ICSR (2 * MAXN + 1)

__device__ __align__(16) float g_bufA[2][MAXN * HDIM];   // also used as packed-u32 h
__device__ __align__(16) float g_bufB[2][MAXN * HDIM];
__device__ int   g_icsr[2][ICSR];     // deg | (unused) | gctr
__device__ int   g_erank[2][MAXE];
__device__ float g_dis[2][MAXN];
__device__ int   g_offs[2][MAXN];
__device__ int   g_csr_col[2][MAXE];
__device__ float g_gsum[2 * HDIM];
// bf16 weight splits: 8 images (w1hi,w1lo,w2hi,w2lo,c1hi,c1lo,c2hi,c2lo) x 8192 u32
__device__ __align__(16) unsigned g_wbf[8][8192];

// ======================= helpers ===========================================
__device__ __forceinline__ uint32_t smem_u32(const void* p) {
    uint32_t a;
    asm("{ .reg .u64 t; cvta.to.shared.u64 t, %1; cvt.u32.u64 %0, t; }" : "=r"(a) : "l"(p));
    return a;
}
__device__ __forceinline__ void ldsm_x4(uint32_t addr, uint32_t r[4]) {
    asm volatile("ldmatrix.sync.aligned.m8n8.x4.shared.b16 {%0,%1,%2,%3}, [%4];"
                 : "=r"(r[0]), "=r"(r[1]), "=r"(r[2]), "=r"(r[3]) : "r"(addr));
}
__device__ __forceinline__ void ldsm_x4t(uint32_t addr, uint32_t r[4]) {
    asm volatile("ldmatrix.sync.aligned.m8n8.x4.trans.shared.b16 {%0,%1,%2,%3}, [%4];"
                 : "=r"(r[0]), "=r"(r[1]), "=r"(r[2]), "=r"(r[3]) : "r"(addr));
}
__device__ __forceinline__ void mma16816(float c[4], const uint32_t a[4],
                                         uint32_t b0, uint32_t b1) {
    asm volatile(
        "mma.sync.aligned.m16n8k16.row.col.f32.bf16.bf16.f32 "
        "{%0,%1,%2,%3}, {%4,%5,%6,%7}, {%8,%9}, {%0,%1,%2,%3};"
        : "+f"(c[0]), "+f"(c[1]), "+f"(c[2]), "+f"(c[3])
        : "r"(a[0]), "r"(a[1]), "r"(a[2]), "r"(a[3]), "r"(b0), "r"(b1));
}
// packed rn split: hi/lo bf16 pairs for 2 fp32 values (low half = v0)
__device__ __forceinline__ void split2(float v0, float v1, unsigned& hi, unsigned& lo) {
    unsigned h;
    asm("cvt.rn.bf16x2.f32 %0, %1, %2;" : "=r"(h) : "f"(v1), "f"(v0));
    float f0 = __uint_as_float(h << 16);
    float f1 = __uint_as_float(h & 0xFFFF0000u);
    float r0 = v0 - f0, r1 = v1 - f1;
    unsigned l;
    asm("cvt.rn.bf16x2.f32 %0, %1, %2;" : "=r"(l) : "f"(r1), "f"(r0));
    hi = h; lo = l;
}
__device__ __forceinline__ unsigned pack_bf16x2(float v0, float v1) {
    unsigned h;
    asm("cvt.rn.bf16x2.f32 %0, %1, %2;" : "=r"(h) : "f"(v1), "f"(v0));
    return h;
}

// ---------------------------------------------------------------------------
// Weight prep: 4 weights, one launch (grid.y selects weight).
// ---------------------------------------------------------------------------
__global__ void k_convw(const float* __restrict__ w0, const float* __restrict__ w1,
                        const float* __restrict__ w2, const float* __restrict__ w3,
                        unsigned* __restrict__ wbf)
{
    int idx = blockIdx.x * blockDim.x + threadIdx.x;   // 8192 = 128k * 64 n-pairs
    if (idx >= 8192) return;
    const float* W = (blockIdx.y == 0) ? w0 : (blockIdx.y == 1) ? w1
                   : (blockIdx.y == 2) ? w2 : w3;
    unsigned* hi = wbf + (size_t)(2 * blockIdx.y) * 8192;
    unsigned* lo = hi + 8192;
    int k = idx >> 6;
    int n = (idx & 63) * 2;
    unsigned h, l;
    split2(W[(size_t)k * 128 + n], W[(size_t)k * 128 + n + 1], h, l);
    hi[idx] = h;
    lo[idx] = l;
}

// ---------------------------------------------------------------------------
// GEMM tiling constants
// ---------------------------------------------------------------------------
#define ASTR 136
#define TH   (128 * ASTR)          // halves per 128-row image
#define TH64 (64 * ASTR)           // halves per 64-row image

// enc3 smem layout (halves): A hi/lo + W slot1 hi/lo + W slot2 hi/lo
#define E_AHI 0
#define E_ALO TH
#define E_B1HI (2 * TH)
#define E_B1LO (3 * TH)
#define E_B2HI (4 * TH)
#define E_B2LO (5 * TH)
#define SM_ENC3 (6 * TH * 2)       // 208896 B

// gemm64 smem layout (halves)
#define G_AHI 0
#define G_ALO TH64
#define G_BHI (2 * TH64)
#define G_BLO (2 * TH64 + TH)
#define SM_G64 ((2 * TH64 + 2 * TH) * 2)   // 104448 B

__device__ __forceinline__ void gemm_mainloop(uint32_t aHi, uint32_t aLo,
                                              uint32_t bHi, uint32_t bLo,
                                              float acc[16][4])
{
#pragma unroll
    for (int ks = 0; ks < 8; ks++) {
        const uint32_t kb = (uint32_t)(ks * 16) * 2u;
        uint32_t ah[4], al[4];
        ldsm_x4(aHi + kb, ah);
        ldsm_x4(aLo + kb, al);
        const uint32_t kRowB = (uint32_t)(ks * 16 * ASTR) * 2u;
#pragma unroll
        for (int nb = 0; nb < 8; nb++) {
            uint32_t bh[4], bl[4];
            const uint32_t nOff = (uint32_t)(nb * 16) * 2u;
            ldsm_x4t(bHi + kRowB + nOff, bh);
            ldsm_x4t(bLo + kRowB + nOff, bl);
            mma16816(acc[nb * 2],     ah, bh[0], bh[1]);
            mma16816(acc[nb * 2 + 1], ah, bh[2], bh[3]);
            mma16816(acc[nb * 2],     ah, bl[0], bl[1]);
            mma16816(acc[nb * 2 + 1], ah, bl[2], bl[3]);
            mma16816(acc[nb * 2],     al, bh[0], bh[1]);
            mma16816(acc[nb * 2 + 1], al, bh[2], bh[3]);
        }
    }
}

// ---------------------------------------------------------------------------
// Fused encoder + conv1: h3 = (relu(X W1 + b1) W2 + b2) W3 + b3
// Output written as packed bf16x2 rows (64 u32 = 256 B per row).
// ---------------------------------------------------------------------------
__global__ __launch_bounds__(256, 1)
void k_enc3(const float* __restrict__ x1, const float* __restrict__ x2,
            const unsigned* __restrict__ wbf,
            const float* __restrict__ b1, const float* __restrict__ b2,
            const float* __restrict__ b3,
            unsigned* __restrict__ C0, int M, int tpg)
{
    extern __shared__ __nv_bfloat16 smh[];
    const uint32_t sb = smem_u32(smh);
    const int tid = threadIdx.x;
    const int wid = tid >> 5, lid = tid & 31;
    const int g = blockIdx.x / tpg;
    const int bm = (blockIdx.x % tpg) * 128;
    const float* X = g ? x2 : x1;
    unsigned* C = C0 + (size_t)g * MAXN * HDIM;   // u32 stride = HDIM (float-array alias)

    // W1 -> slot1, W2 -> slot2
    for (int i = tid; i < 8192; i += 256) {
        int k = i >> 6, np = i & 63;
        int o = k * ASTR + np * 2;
        *(unsigned*)(smh + E_B1HI + o) = __ldg(wbf + i);
        *(unsigned*)(smh + E_B1LO + o) = __ldg(wbf + 8192 + i);
        *(unsigned*)(smh + E_B2HI + o) = __ldg(wbf + 16384 + i);
        *(unsigned*)(smh + E_B2LO + o) = __ldg(wbf + 24576 + i);
    }
    // A tile (128x128 fp32 -> hi/lo)
    for (int i = tid; i < 4096; i += 256) {
        int r = i >> 5, c4 = (i & 31) * 4;
        int grow = bm + r;
        float4 v = make_float4(0.f, 0.f, 0.f, 0.f);
        if (grow < M) v = *(const float4*)(X + (size_t)grow * 128 + c4);
        unsigned h0, l0, h1, l1;
        split2(v.x, v.y, h0, l0);
        split2(v.z, v.w, h1, l1);
        unsigned* ph = (unsigned*)(smh + E_AHI + r * ASTR + c4);
        unsigned* pl = (unsigned*)(smh + E_ALO + r * ASTR + c4);
        ph[0] = h0; ph[1] = h1;
        pl[0] = l0; pl[1] = l1;
    }
    __syncthreads();

    const int wr = wid * 16;
    const int sub = lid >> 3, l7 = lid & 7;
    const uint32_t aHi = sb + (uint32_t)(E_AHI + (wr + (sub & 1) * 8 + l7) * ASTR + (sub >> 1) * 8) * 2u;
    const uint32_t aLo = aHi + (uint32_t)(TH * 2);
    const uint32_t bOff = (uint32_t)(((sub & 1) * 8 + l7) * ASTR + (sub >> 1) * 8) * 2u;
    const uint32_t b1Hi = sb + (uint32_t)(E_B1HI) * 2u + bOff;
    const uint32_t b1Lo = sb + (uint32_t)(E_B1LO) * 2u + bOff;
    const uint32_t b2Hi = sb + (uint32_t)(E_B2HI) * 2u + bOff;
    const uint32_t b2Lo = sb + (uint32_t)(E_B2LO) * 2u + bOff;

    const int gid = lid >> 2, tig = lid & 3;
    const int r0 = wr + gid;
    const int r1 = r0 + 8;

    float acc[16][4];
#pragma unroll
    for (int i = 0; i < 16; i++)
#pragma unroll
        for (int j = 0; j < 4; j++) acc[i][j] = 0.0f;

    // ---- GEMM 1: relu(X W1 + b1) -> A ----
    gemm_mainloop(aHi, aLo, b1Hi, b1Lo, acc);
#pragma unroll
    for (int nb = 0; nb < 16; nb++) {
        int col = nb * 8 + tig * 2;
        float2 bv = *(const float2*)(b1 + col);
        float v0 = fmaxf(acc[nb][0] + bv.x, 0.f);
        float v1 = fmaxf(acc[nb][1] + bv.y, 0.f);
        float v2 = fmaxf(acc[nb][2] + bv.x, 0.f);
        float v3 = fmaxf(acc[nb][3] + bv.y, 0.f);
        unsigned h, l;
        split2(v0, v1, h, l);
        *(unsigned*)(smh + E_AHI + r0 * ASTR + col) = h;
        *(unsigned*)(smh + E_ALO + r0 * ASTR + col) = l;
        split2(v2, v3, h, l);
        *(unsigned*)(smh + E_AHI + r1 * ASTR + col) = h;
        *(unsigned*)(smh + E_ALO + r1 * ASTR + col) = l;
        acc[nb][0] = 0.f; acc[nb][1] = 0.f; acc[nb][2] = 0.f; acc[nb][3] = 0.f;
    }
    __syncwarp();

    // ---- GEMM 2: (.) W2 + b2 -> A  (no relu) ----
    gemm_mainloop(aHi, aLo, b2Hi, b2Lo, acc);
#pragma unroll
    for (int nb = 0; nb < 16; nb++) {
        int col = nb * 8 + tig * 2;
        float2 bv = *(const float2*)(b2 + col);
        float v0 = acc[nb][0] + bv.x;
        float v1 = acc[nb][1] + bv.y;
        float v2 = acc[nb][2] + bv.x;
        float v3 = acc[nb][3] + bv.y;
        unsigned h, l;
        split2(v0, v1, h, l);
        *(unsigned*)(smh + E_AHI + r0 * ASTR + col) = h;
        *(unsigned*)(smh + E_ALO + r0 * ASTR + col) = l;
        split2(v2, v3, h, l);
        *(unsigned*)(smh + E_AHI + r1 * ASTR + col) = h;
        *(unsigned*)(smh + E_ALO + r1 * ASTR + col) = l;
        acc[nb][0] = 0.f; acc[nb][1] = 0.f; acc[nb][2] = 0.f; acc[nb][3] = 0.f;
    }

    // ---- reload W3 (conv1) into slot1 ----
    __syncthreads();
    for (int i = tid; i < 8192; i += 256) {
        int k = i >> 6, np = i & 63;
        int o = k * ASTR + np * 2;
        *(unsigned*)(smh + E_B1HI + o) = __ldg(wbf + 32768 + i);
        *(unsigned*)(smh + E_B1LO + o) = __ldg(wbf + 40960 + i);
    }
    __syncthreads();

    // ---- GEMM 3: (.) W3 + b3 -> gmem (packed bf16x2) ----
    gemm_mainloop(aHi, aLo, b1Hi, b1Lo, acc);
    const int row0 = bm + r0;
    const int row1 = bm + r1;
#pragma unroll
    for (int nb = 0; nb < 16; nb++) {
        int col = nb * 8 + tig * 2;
        float2 bv = *(const float2*)(b3 + col);
        int ci = nb * 4 + tig;   // u32 column index (col/2)
        if (row0 < M)
            C[(size_t)row0 * 64 + ci] = pack_bf16x2(acc[nb][0] + bv.x, acc[nb][1] + bv.y);
        if (row1 < M)
            C[(size_t)row1 * 64 + ci] = pack_bf16x2(acc[nb][2] + bv.x, acc[nb][3] + bv.y);
    }
}

// ---------------------------------------------------------------------------
// GCN-2 GEMM, BM=64 / 128 threads (2 CTAs/SM): C = relu(dis*A) @ W + bias
// fp32 input (agg), packed bf16x2 output.
// ---------------------------------------------------------------------------
__global__ __launch_bounds__(128, 2)
void k_gemm64(const float* __restrict__ A0,
              const unsigned* __restrict__ whi, const unsigned* __restrict__ wlo,
              const float* __restrict__ bias, unsigned* __restrict__ C0,
              const float* __restrict__ dis0, int M, int tpg)
{
    extern __shared__ __nv_bfloat16 smh[];
    const uint32_t sb = smem_u32(smh);
    const int tid = threadIdx.x;
    const int wid = tid >> 5, lid = tid & 31;
    const int g = blockIdx.x / tpg;
    const int bm = (blockIdx.x % tpg) * 64;
    const float* A   = A0 + (size_t)g * MAXN * HDIM;
    unsigned* C      = C0 + (size_t)g * MAXN * HDIM;
    const float* dis = dis0 + (size_t)g * MAXN;

    for (int i = tid; i < 8192; i += 128) {
        int k = i >> 6, np = i & 63;
        int o = k * ASTR + np * 2;
        *(unsigned*)(smh + G_BHI + o) = __ldg(whi + i);
        *(unsigned*)(smh + G_BLO + o) = __ldg(wlo + i);
    }
    for (int i = tid; i < 2048; i += 128) {            // 64 rows x 32 float4
        int r = i >> 5, c4 = (i & 31) * 4;
        int grow = bm + r;
        float4 v = make_float4(0.f, 0.f, 0.f, 0.f);
        if (grow < M) {
            v = *(const float4*)(A + (size_t)grow * 128 + c4);
            float dv = dis[grow];
            v.x = fmaxf(v.x * dv, 0.f); v.y = fmaxf(v.y * dv, 0.f);
            v.z = fmaxf(v.z * dv, 0.f); v.w = fmaxf(v.w * dv, 0.f);
        }
        unsigned h0, l0, h1, l1;
        split2(v.x, v.y, h0, l0);
        split2(v.z, v.w, h1, l1);
        unsigned* ph = (unsigned*)(smh + G_AHI + r * ASTR + c4);
        unsigned* pl = (unsigned*)(smh + G_ALO + r * ASTR + c4);
        ph[0] = h0; ph[1] = h1;
        pl[0] = l0; pl[1] = l1;
    }
    __syncthreads();

    const int wr = wid * 16;
    const int sub = lid >> 3, l7 = lid & 7;
    const uint32_t aHi = sb + (uint32_t)(G_AHI + (wr + (sub & 1) * 8 + l7) * ASTR + (sub >> 1) * 8) * 2u;
    const uint32_t aLo = aHi + (uint32_t)(TH64 * 2);
    const uint32_t bHi = sb + (uint32_t)(G_BHI + ((sub & 1) * 8 + l7) * ASTR + (sub >> 1) * 8) * 2u;
    const uint32_t bLo = bHi + (uint32_t)(TH * 2);

    float acc[16][4];
#pragma unroll
    for (int i = 0; i < 16; i++)
#pragma unroll
        for (int j = 0; j < 4; j++) acc[i][j] = 0.0f;

    gemm_mainloop(aHi, aLo, bHi, bLo, acc);

    const int gid = lid >> 2, tig = lid & 3;
    const int row0 = bm + wr + gid;
    const int row1 = row0 + 8;
#pragma unroll
    for (int nb = 0; nb < 16; nb++) {
        int col = nb * 8 + tig * 2;
        float2 bv = *(const float2*)(bias + col);
        int ci = nb * 4 + tig;
        if (row0 < M)
            C[(size_t)row0 * 64 + ci] = pack_bf16x2(acc[nb][0] + bv.x, acc[nb][1] + bv.y);
        if (row1 < M)
            C[(size_t)row1 * 64 + ci] = pack_bf16x2(acc[nb][2] + bv.x, acc[nb][3] + bv.y);
    }
}

// ---------------------------------------------------------------------------
// CSR build (both graphs per launch via grid.y); degree pass captures ranks
// ---------------------------------------------------------------------------
__global__ void k_deg2(const int* __restrict__ ei1, const int* __restrict__ ei2,
                       int E, int* __restrict__ icsr0, int* __restrict__ erank0)
{
    int e = blockIdx.x * blockDim.x + threadIdx.x;
    if (e >= E) return;
    const int* ei = blockIdx.y ? ei2 : ei1;
    int* deg = icsr0 + (size_t)blockIdx.y * ICSR;
    int* erank = erank0 + (size_t)blockIdx.y * MAXE;
    erank[e] = atomicAdd(&deg[ei[e]], 1);
}

__global__ void k_dis_offs2(int* __restrict__ icsr0, float* __restrict__ dis0,
                            int* __restrict__ offs0, int n)
{
    int i = blockIdx.x * blockDim.x + threadIdx.x;
    if (i >= n) return;
    int* deg  = icsr0 + (size_t)blockIdx.y * ICSR;
    int* gctr = deg + 2 * MAXN;
    float* dis = dis0 + (size_t)blockIdx.y * MAXN;
    int*   offs = offs0 + (size_t)blockIdx.y * MAXN;
    int d = deg[i];
    dis[i] = (d > 0) ? rsqrtf((float)d) : 0.0f;
    offs[i] = atomicAdd(gctr, d);
}

__global__ void k_scatter2(const int* __restrict__ ei1, const int* __restrict__ ei2,
                           int E, const int* __restrict__ offs0,
                           const int* __restrict__ erank0, int* __restrict__ cols0)
{
    int e = blockIdx.x * blockDim.x + threadIdx.x;
    if (e >= E) return;
    const int* ei = blockIdx.y ? ei2 : ei1;
    const int* offs = offs0 + (size_t)blockIdx.y * MAXN;
    const int* erank = erank0 + (size_t)blockIdx.y * MAXE;
    int* cols = cols0 + (size_t)blockIdx.y * MAXE;
    int r = ei[e];
    int c = ei[E + e];
    cols[offs[r] + erank[e]] = c;
}

// ---------------------------------------------------------------------------
// edge-gather inner step (packed bf16x2 h rows, 256 B/row)
// ---------------------------------------------------------------------------
__device__ __forceinline__ void agg_step(const unsigned* __restrict__ h,
                                         const int* __restrict__ cols,
                                         const float* __restrict__ dis,
                                         int i, int lane, float4& a)
{
    int c = __ldg(cols + i);
    float nr = __ldg(dis + c);
    uint2 p = __ldg((const uint2*)(h + (size_t)c * 64) + lane);
    float2 f0 = __bfloat1622float2(*reinterpret_cast<const __nv_bfloat162*>(&p.x));
    float2 f1 = __bfloat1622float2(*reinterpret_cast<const __nv_bfloat162*>(&p.y));
    a.x = fmaf(nr, f0.x, a.x); a.y = fmaf(nr, f0.y, a.y);
    a.z = fmaf(nr, f1.x, a.z); a.w = fmaf(nr, f1.y, a.w);
}

// ---------------------------------------------------------------------------
// CSR aggregation (batched, 4-way unrolled): agg[n,:] = sum dis[c]*h[c,:]
// ---------------------------------------------------------------------------
__global__ void k_aggregate(const unsigned* __restrict__ h0,
                            const int* __restrict__ offs0, const int* __restrict__ icsr0,
                            const int* __restrict__ cols0,
                            const float* __restrict__ dis0,
                            float* __restrict__ agg0, int n, int bpg)
{
    const int g = blockIdx.x / bpg;
    const int lb = blockIdx.x % bpg;
    int warp = lb * (blockDim.x >> 5) + (threadIdx.x >> 5);
    int lane = threadIdx.x & 31;
    if (warp >= n) return;
    const unsigned* h = h0    + (size_t)g * MAXN * HDIM;
    float* agg        = agg0  + (size_t)g * MAXN * HDIM;
    const int* offs   = offs0 + (size_t)g * MAXN;
    const int* deg    = icsr0 + (size_t)g * ICSR;
    const int* cols   = cols0 + (size_t)g * MAXE;
    const float* dis  = dis0  + (size_t)g * MAXN;

    int s = __ldg(offs + warp);
    int e = s + __ldg(deg + warp);
    float4 a0 = make_float4(0.f, 0.f, 0.f, 0.f);
    float4 a1 = make_float4(0.f, 0.f, 0.f, 0.f);
    float4 a2 = make_float4(0.f, 0.f, 0.f, 0.f);
    float4 a3 = make_float4(0.f, 0.f, 0.f, 0.f);
    int i = s;
    for (; i + 4 <= e; i += 4) {
        agg_step(h, cols, dis, i + 0, lane, a0);
        agg_step(h, cols, dis, i + 1, lane, a1);
        agg_step(h, cols, dis, i + 2, lane, a2);
        agg_step(h, cols, dis, i + 3, lane, a3);
    }
    if (i + 2 <= e) {
        agg_step(h, cols, dis, i + 0, lane, a0);
        agg_step(h, cols, dis, i + 1, lane, a1);
        i += 2;
    }
    if (i < e) agg_step(h, cols, dis, i, lane, a0);
    a0.x += a1.x + a2.x + a3.x;
    a0.y += a1.y + a2.y + a3.y;
    a0.z += a1.z + a2.z + a3.z;
    a0.w += a1.w + a2.w + a3.w;
    *(float4*)(agg + (size_t)warp * 128 + lane * 4) = a0;
}

// ---------------------------------------------------------------------------
// Fused aggregate + mean-pool (layer 2, batched, 4-way unrolled)
// ---------------------------------------------------------------------------
__global__ void k_aggpool(const unsigned* __restrict__ h0,
                          const int* __restrict__ offs0, const int* __restrict__ icsr0,
                          const int* __restrict__ cols0,
                          const float* __restrict__ dis0,
                          float* __restrict__ gsum0, int n, int bpg)
{
    __shared__ float gpart[128];
    if (threadIdx.x < 128) gpart[threadIdx.x] = 0.0f;
    __syncthreads();

    const int g = blockIdx.x / bpg;
    const int lb = blockIdx.x % bpg;
    int warp = lb * (blockDim.x >> 5) + (threadIdx.x >> 5);
    int lane = threadIdx.x & 31;
    const unsigned* h = h0    + (size_t)g * MAXN * HDIM;
    const int* offs   = offs0 + (size_t)g * MAXN;
    const int* deg    = icsr0 + (size_t)g * ICSR;
    const int* cols   = cols0 + (size_t)g * MAXE;
    const float* dis  = dis0  + (size_t)g * MAXN;
    float* gsum       = gsum0 + (size_t)g * HDIM;

    if (warp < n) {
        int s = __ldg(offs + warp);
        int e = s + __ldg(deg + warp);
        float4 a0 = make_float4(0.f, 0.f, 0.f, 0.f);
        float4 a1 = make_float4(0.f, 0.f, 0.f, 0.f);
        float4 a2 = make_float4(0.f, 0.f, 0.f, 0.f);
        float4 a3 = make_float4(0.f, 0.f, 0.f, 0.f);
        int i = s;
        for (; i + 4 <= e; i += 4) {
            agg_step(h, cols, dis, i + 0, lane, a0);
            agg_step(h, cols, dis, i + 1, lane, a1);
            agg_step(h, cols, dis, i + 2, lane, a2);
            agg_step(h, cols, dis, i + 3, lane, a3);
        }
        if (i + 2 <= e) {
            agg_step(h, cols, dis, i + 0, lane, a0);
            agg_step(h, cols, dis, i + 1, lane, a1);
            i += 2;
        }
        if (i < e) agg_step(h, cols, dis, i, lane, a0);
        float d = __ldg(dis + warp);
        atomicAdd(&gpart[lane * 4 + 0], fmaxf(d * (a0.x + a1.x + a2.x + a3.x), 0.f));
        atomicAdd(&gpart[lane * 4 + 1], fmaxf(d * (a0.y + a1.y + a2.y + a3.y), 0.f));
        atomicAdd(&gpart[lane * 4 + 2], fmaxf(d * (a0.z + a1.z + a2.z + a3.z), 0.f));
        atomicAdd(&gpart[lane * 4 + 3], fmaxf(d * (a0.w + a1.w + a2.w + a3.w), 0.f));
    }
    __syncthreads();
    if (threadIdx.x < 128) {
        float v = gpart[threadIdx.x];
        if (v != 0.0f) atomicAdd(&gsum[threadIdx.x], v);
    }
}

// ---------------------------------------------------------------------------
// final MLP
// ---------------------------------------------------------------------------
__global__ void k_final(const float* __restrict__ gsum,
                        const float* __restrict__ w1, const float* __restrict__ b1,
                        const float* __restrict__ w2, const float* __restrict__ b2,
                        float* __restrict__ out, float invN)
{
    __shared__ float cv[512];
    __shared__ float red[128];
    int t = threadIdx.x;
    float a = gsum[t] * invN;
    float b = gsum[128 + t] * invN;
    cv[t]       = a;
    cv[128 + t] = b;
    cv[256 + t] = fabsf(a - b);
    cv[384 + t] = a * b;
    __syncthreads();
    float acc = b1[t];
    for (int k = 0; k < 512; k++)
        acc = fmaf(cv[k], w1[k * 128 + t], acc);
    acc = fmaxf(acc, 0.f);
    red[t] = acc * w2[t];
    __syncthreads();
    for (int s = 64; s > 0; s >>= 1) {
        if (t < s) red[t] += red[t + s];
        __syncthreads();
    }
    if (t == 0) out[0] = red[0] + b2[0];
}

// ---------------------------------------------------------------------------
// launch — single stream, both graphs batched per kernel
// ---------------------------------------------------------------------------
extern "C" void kernel_launch(void* const* d_in, const int* in_sizes, int n_in,
                              void* d_out, int out_size)
{
    const float* x1  = (const float*)d_in[0];
    const int*   ei1 = (const int*)d_in[1];
    const float* x2  = (const float*)d_in[2];
    const int*   ei2 = (const int*)d_in[3];
    const float* enc_w1 = (const float*)d_in[4];
    const float* enc_b1 = (const float*)d_in[5];
    const float* enc_w2 = (const float*)d_in[6];
    const float* enc_b2 = (const float*)d_in[7];
    const float* conv1_w = (const float*)d_in[8];
    const float* conv1_b = (const float*)d_in[9];
    const float* conv2_w = (const float*)d_in[10];
    const float* conv2_b = (const float*)d_in[11];
    const float* sim_w1 = (const float*)d_in[12];
    const float* sim_b1 = (const float*)d_in[13];
    const float* sim_w2 = (const float*)d_in[14];
    const float* sim_b2 = (const float*)d_in[15];

    const int n = in_sizes[0] / HDIM;
    const int E = in_sizes[1] / 2;

    float *bufA, *bufB, *dis, *gsum;
    int *icsr, *offs, *cols, *erank;
    unsigned* wbf;
    cudaGetSymbolAddress((void**)&bufA,  g_bufA);
    cudaGetSymbolAddress((void**)&bufB,  g_bufB);
    cudaGetSymbolAddress((void**)&icsr,  g_icsr);
    cudaGetSymbolAddress((void**)&erank, g_erank);
    cudaGetSymbolAddress((void**)&dis,   g_dis);
    cudaGetSymbolAddress((void**)&offs,  g_offs);
    cudaGetSymbolAddress((void**)&cols,  g_csr_col);
    cudaGetSymbolAddress((void**)&gsum,  g_gsum);
    cudaGetSymbolAddress((void**)&wbf,   g_wbf);

    cudaFuncSetAttribute(k_enc3,   cudaFuncAttributeMaxDynamicSharedMemorySize, SM_ENC3);
    cudaFuncSetAttribute(k_gemm64, cudaFuncAttributeMaxDynamicSharedMemorySize, SM_G64);

    const int tpg128   = (n + 127) / 128;          // 128-row tiles per graph
    const int tpg64    = (n + 63) / 64;            // 64-row tiles per graph
    const int eBlocks  = (E + 255) / 256;
    const int nBlocks  = (n + 255) / 256;
    const int bpg      = (n * 32 + 255) / 256;     // aggregate blocks per graph

    // --- prep ---
    cudaMemsetAsync(gsum, 0, 2 * HDIM * sizeof(float));
    cudaMemsetAsync(icsr, 0, 2 * ICSR * sizeof(int));
    {
        dim3 grid(32, 4);
        k_convw<<<grid, 256>>>(enc_w1, enc_w2, conv1_w, conv2_w, wbf);
    }

    // --- CSR build (both graphs) ---
    {
        dim3 gE(eBlocks, 2), gN(nBlocks, 2);
        k_deg2<<<gE, 256>>>(ei1, ei2, E, icsr, erank);
        k_dis_offs2<<<gN, 256>>>(icsr, dis, offs, n);
        k_scatter2<<<gE, 256>>>(ei1, ei2, E, offs, erank, cols);
    }

    // --- fused encoder + conv1 (both graphs) -> bufA (packed bf16x2) ---
    k_enc3<<<2 * tpg128, 256, SM_ENC3>>>(x1, x2, wbf, enc_b1, enc_b2, conv1_b,
                                         (unsigned*)bufA, n, tpg128);

    // --- aggregate 1 -> bufB (fp32) ---
    k_aggregate<<<2 * bpg, 256>>>((const unsigned*)bufA, offs, icsr, cols, dis,
                                  bufB, n, bpg);

    // --- GCN layer 2 GEMM (relu(dis*agg) fused) -> bufA (packed bf16x2) ---
    k_gemm64<<<2 * tpg64, 128, SM_G64>>>(bufB, wbf + 6 * 8192, wbf + 7 * 8192,
                                         conv2_b, (unsigned*)bufA, dis, n, tpg64);

    // --- aggregate 2 + mean pool -> gsum ---
    k_aggpool<<<2 * bpg, 256>>>((const unsigned*)bufA, offs, icsr, cols, dis,
                                gsum, n, bpg);

    // --- final MLP ---
    k_final<<<1, 128>>>(gsum, sim_w1, sim_b1, sim_w2, sim_b2,
                        (float*)d_out, 1.0f / (float)n);
}